// round 10
// baseline (speedup 1.0000x reference)
#include <cuda_runtime.h>
#include <cuda_bf16.h>
#include <cstdint>
#include <math.h>

#define TT 2048
#define HIDDEN 2048
#define NH 16
#define DN 128
#define DR 64
#define DVV 128
#define KV_LORA 512
#define DQ (DN + DR)          // 192
#define QW (NH * DQ)          // 3072
#define KVW (NH * (DN + DVV)) // 4096
#define LATW (KV_LORA + DR)   // 576

// ---------------- scratch ----------------------------------------------------
__device__ float g_q[TT * QW];
__device__ float g_latent[TT * LATW];
__device__ float g_kva[TT * KV_LORA];
__device__ float g_kpe[TT * DR];
__device__ float g_kv[TT * KVW];
__device__ float g_attn[TT * NH * DVV];
// pre-rounded (tf32-valued) copies of inputs
__device__ float g_hid_r[TT * HIDDEN];
__device__ float g_wq_r[HIDDEN * QW];
__device__ float g_wkva_r[HIDDEN * LATW];
__device__ float g_wkvb_r[KV_LORA * KVW];
__device__ float g_wo_r[NH * DVV * HIDDEN];

// ---------------- helpers -----------------------------------------------------
__device__ __forceinline__ uint32_t f2tf32(float x) {
    uint32_t r;
    asm("cvt.rna.tf32.f32 %0, %1;" : "=r"(r) : "f"(x));
    return r;
}
__device__ __forceinline__ float f2tf32f(float x) { return __uint_as_float(f2tf32(x)); }

__device__ __forceinline__ void mma_tf32(float c[4], const uint32_t a[4], const uint32_t b[2]) {
    asm volatile(
        "mma.sync.aligned.m16n8k8.row.col.f32.tf32.tf32.f32 "
        "{%0,%1,%2,%3}, {%4,%5,%6,%7}, {%8,%9}, {%0,%1,%2,%3};"
        : "+f"(c[0]), "+f"(c[1]), "+f"(c[2]), "+f"(c[3])
        : "r"(a[0]), "r"(a[1]), "r"(a[2]), "r"(a[3]), "r"(b[0]), "r"(b[1]));
}

__device__ __forceinline__ uint32_t smem_u32(const void* p) {
    return (uint32_t)__cvta_generic_to_shared(p);
}
__device__ __forceinline__ void cp16(uint32_t dst, const void* src, int src_bytes) {
    asm volatile("cp.async.cg.shared.global [%0], [%1], 16, %2;"
                 :: "r"(dst), "l"(src), "r"(src_bytes));
}
__device__ __forceinline__ void cp4(uint32_t dst, const void* src) {
    asm volatile("cp.async.ca.shared.global [%0], [%1], 4;"
                 :: "r"(dst), "l"(src));
}
#define CP_COMMIT() asm volatile("cp.async.commit_group;")
#define CP_WAIT(n)  asm volatile("cp.async.wait_group %0;" :: "n"(n))

// K-dim permutation within 8-word groups: frag pairs (tig, tig+4) -> adjacent
__device__ __forceinline__ int kperm(int d) {
    return (d & ~7) + 2 * (d & 3) + ((d >> 2) & 1);
}

__device__ __forceinline__ void rope_pair(float p, int i, float& x1, float& x2) {
    float inv = 1.0f / powf(10000.0f, (float)(2 * i) / (float)DR);
    float f = p * inv;
    float c = cosf(f), s = sinf(f);
    float o1 = x1 * c - x2 * s;
    float o2 = x2 * c + x1 * s;
    x1 = o1; x2 = o2;
}

// ---------------- pre-round inputs to tf32 values -------------------------------
__global__ __launch_bounds__(256) void round_copy(
    const float* __restrict__ in, float* __restrict__ out, int n4)
{
    int i = blockIdx.x * 256 + threadIdx.x;
    if (i < n4) {
        float4 v = reinterpret_cast<const float4*>(in)[i];
        float4 o;
        o.x = f2tf32f(v.x); o.y = f2tf32f(v.y);
        o.z = f2tf32f(v.z); o.w = f2tf32f(v.w);
        reinterpret_cast<float4*>(out)[i] = o;
    }
}

// ---------------- TF32 GEMM: pre-rounded inputs, permuted A, v2 a-frags ---------
#define GSTAGES 4
#define GA_STRIDE 40
#define GB_STRIDE 264
#define GAW (128 * GA_STRIDE)            // 5120 words
#define GBW (32 * GB_STRIDE)             // 8448 words
#define GSTAGE_W (GAW + GBW)             // 13568 words
#define GEMM_SMEM (GSTAGES * GSTAGE_W * 4)  // 217088 B

__global__ __launch_bounds__(256, 1) void gemm_tf32_dual(
    const float* __restrict__ A,
    const float* __restrict__ B1, float* __restrict__ C1, int N1,
    const float* __restrict__ B2, float* __restrict__ C2, int N2,
    int K, int roundC)
{
    extern __shared__ float gsm[];
    const uint32_t smBase = smem_u32(gsm);

    const int tiles1 = (N1 + 255) / 256;
    const float* B; float* C; int N, n0;
    if ((int)blockIdx.x < tiles1) {
        B = B1; C = C1; N = N1; n0 = blockIdx.x * 256;
    } else {
        B = B2; C = C2; N = N2; n0 = (blockIdx.x - tiles1) * 256;
    }

    const int tid  = threadIdx.x;
    const int lane = tid & 31, warp = tid >> 5;
    const int warpM = warp & 1;
    const int warpN = warp >> 1;
    const int gid = lane >> 2, tig = lane & 3;
    const int m0 = blockIdx.y * 128;

    const int br = tid >> 6, bc = (tid & 63) * 4;

    const int nslab = K >> 5;

    auto issue_slab = [&](int slab) {
        const int k0 = slab * 32;
        const uint32_t stg = smBase + (uint32_t)((slab & (GSTAGES - 1)) * GSTAGE_W) * 4;
        // A: 128 rows x 32 words, 4B cp.async with K-perm within 8-word groups
        #pragma unroll
        for (int i = 0; i < 16; i++) {
            int w = i * 256 + tid;           // 0..4095
            int r = w >> 5, d = w & 31;
            uint32_t dst = stg + (uint32_t)(r * GA_STRIDE + kperm(d)) * 4;
            cp4(dst, &A[(size_t)(m0 + r) * K + k0 + d]);
        }
        // B: raw layout, 16B chunks
        const int col = n0 + bc;
        const int ok = (col < N) ? 16 : 0;
        #pragma unroll
        for (int i = 0; i < 8; i++) {
            uint32_t dst = stg + (uint32_t)(GAW + (br + 4 * i) * GB_STRIDE + bc) * 4;
            cp16(dst, &B[(size_t)(k0 + br + 4 * i) * N + col], ok);
        }
    };

    #pragma unroll
    for (int s = 0; s < GSTAGES - 1; s++) {
        if (s < nslab) issue_slab(s);
        CP_COMMIT();
    }

    float c[4][8][4] = {};

    for (int i = 0; i < nslab; i++) {
        CP_WAIT(GSTAGES - 2);
        __syncthreads();

        if (i + GSTAGES - 1 < nslab) issue_slab(i + GSTAGES - 1);
        CP_COMMIT();

        const uint32_t* Ab = (const uint32_t*)(gsm + (i & (GSTAGES - 1)) * GSTAGE_W);
        const uint32_t* Bb = Ab + GAW;

        #pragma unroll
        for (int ks = 0; ks < 4; ks++) {
            const int kb = ks * 8;
            uint32_t a[4][4], b[8][2];
            #pragma unroll
            for (int mt = 0; mt < 4; mt++) {
                int r = warpM * 64 + mt * 16 + gid;
                uint2 aA = *reinterpret_cast<const uint2*>(&Ab[r * GA_STRIDE + kb + 2 * tig]);
                uint2 aB = *reinterpret_cast<const uint2*>(&Ab[(r + 8) * GA_STRIDE + kb + 2 * tig]);
                a[mt][0] = aA.x; a[mt][2] = aA.y;
                a[mt][1] = aB.x; a[mt][3] = aB.y;
            }
            #pragma unroll
            for (int nt = 0; nt < 8; nt++) {
                int cc = warpN * 64 + nt * 8 + gid;
                b[nt][0] = Bb[(kb + tig) * GB_STRIDE + cc];
                b[nt][1] = Bb[(kb + tig + 4) * GB_STRIDE + cc];
            }
            #pragma unroll
            for (int mt = 0; mt < 4; mt++)
                #pragma unroll
                for (int nt = 0; nt < 8; nt++)
                    mma_tf32(c[mt][nt], a[mt], b[nt]);
        }
    }

    #pragma unroll
    for (int mt = 0; mt < 4; mt++) {
        #pragma unroll
        for (int nt = 0; nt < 8; nt++) {
            int r = m0 + warpM * 64 + mt * 16 + gid;
            int cc = n0 + warpN * 64 + nt * 8 + tig * 2;
            if (cc < N) {
                float v0 = c[mt][nt][0], v1 = c[mt][nt][1];
                float v2 = c[mt][nt][2], v3 = c[mt][nt][3];
                if (roundC) {
                    v0 = f2tf32f(v0); v1 = f2tf32f(v1);
                    v2 = f2tf32f(v2); v3 = f2tf32f(v3);
                }
                *reinterpret_cast<float2*>(&C[(size_t)r * N + cc]) = make_float2(v0, v1);
                *reinterpret_cast<float2*>(&C[(size_t)(r + 8) * N + cc]) = make_float2(v2, v3);
            }
        }
    }
}

// ---------------- rmsnorm + rope_k fused (outputs tf32-rounded) -----------------
__global__ __launch_bounds__(256) void rmsnorm_ropek_kernel(
    const float* __restrict__ latent, const float* __restrict__ w,
    float* __restrict__ out, float* __restrict__ kpe)
{
    const int t = blockIdx.x;
    const float* x = latent + (size_t)t * LATW;
    __shared__ float red[8];
    float ss = 0.f;
    for (int i = threadIdx.x; i < KV_LORA; i += 256) { float v = x[i]; ss += v * v; }
    #pragma unroll
    for (int o = 16; o > 0; o >>= 1) ss += __shfl_xor_sync(~0u, ss, o);
    if ((threadIdx.x & 31) == 0) red[threadIdx.x >> 5] = ss;
    __syncthreads();
    if (threadIdx.x == 0) {
        float v = 0.f;
        #pragma unroll
        for (int i = 0; i < 8; i++) v += red[i];
        red[0] = v;
    }
    __syncthreads();
    const float inv = rsqrtf(red[0] / (float)KV_LORA + 1e-6f);
    for (int i = threadIdx.x; i < KV_LORA; i += 256)
        out[(size_t)t * KV_LORA + i] = f2tf32f(x[i] * inv * w[i]);

    if (threadIdx.x < DR / 2) {
        int i = threadIdx.x;
        float x1 = x[KV_LORA + 2 * i], x2 = x[KV_LORA + 2 * i + 1];
        rope_pair((float)t, i, x1, x2);
        kpe[(size_t)t * DR + 2 * i]     = f2tf32f(x1);
        kpe[(size_t)t * DR + 2 * i + 1] = f2tf32f(x2);
    }
}

// ---------------- tensor-core flash attention -----------------------------------
// sQ/sP use permuted K layout + v2 frag loads; sK/sV raw (cp.async-fed).
#define ABM 128
#define ABN 64
#define SQP 200         // sQ row stride (perm + v2 conflict-free)
#define DKP (DQ + 4)    // 196, sK row stride
#define DVP (DVV + 8)   // 136, sV row stride
#define BNP 72          // sP row stride (perm + v2 conflict-free)
#define SQ_W (ABM * SQP)   // 25600
#define SK_W (ABN * DKP)   // 12544
#define SV_W (ABN * DVP)   // 8704
#define SP_W (ABM * BNP)   // 9216
#define ATTN_SMEM ((SQ_W + SK_W + SV_W + SP_W) * 4)  // 224256 B

__global__ __launch_bounds__(256) void mla_attn_tc(
    const float* __restrict__ q, const float* __restrict__ kv,
    const float* __restrict__ kpe, float* __restrict__ out)
{
    extern __shared__ uint32_t asm_[];
    uint32_t* sQ = asm_;
    uint32_t* sK = asm_ + SQ_W;
    uint32_t* sV = asm_ + SQ_W + SK_W;
    uint32_t* sP = asm_ + SQ_W + SK_W + SV_W;
    const uint32_t sKb = smem_u32(sK);
    const uint32_t sVb = smem_u32(sV);

    const int bx = (TT / ABM - 1) - ((int)blockIdx.x >> 4);  // LPT order
    const int h  = (int)blockIdx.x & (NH - 1);
    const int q0 = bx * ABM;
    const int tid = threadIdx.x;
    const int lane = tid & 31, warp = tid >> 5;
    const int gid = lane >> 2, tig = lane & 3;
    const int r0 = warp * 16;
    const float scale = rsqrtf((float)DQ);

    auto issueK = [&](int k0) {
        #pragma unroll
        for (int j = 0; j < 12; j++) {
            int c = j * 256 + tid;
            int r = c / 48, col4 = (c % 48) * 4;
            uint32_t dst = sKb + (uint32_t)(r * DKP + col4) * 4;
            const float* src = (col4 < DN)
                ? &kv[(size_t)(k0 + r) * KVW + h * (DN + DVV) + col4]
                : &kpe[(size_t)(k0 + r) * DR + (col4 - DN)];
            cp16(dst, src, 16);
        }
    };
    auto issueV = [&](int k0) {
        #pragma unroll
        for (int j = 0; j < 8; j++) {
            int c = j * 256 + tid;
            int r = c / 32, col4 = (c % 32) * 4;
            uint32_t dst = sVb + (uint32_t)(r * DVP + col4) * 4;
            cp16(dst, &kv[(size_t)(k0 + r) * KVW + h * (DN + DVV) + DN + col4], 16);
        }
    };

    issueK(0);
    CP_COMMIT();

    // Q nope part (scaled + rounded, perm layout)
    for (int idx = tid; idx < ABM * DN; idx += 256) {
        int r = idx / DN, d = idx % DN;
        sQ[r * SQP + kperm(d)] = f2tf32(q[(size_t)(q0 + r) * QW + h * DQ + d] * scale);
    }
    // Q pe part with fused rope (perm layout)
    for (int idx = tid; idx < ABM * (DR / 2); idx += 256) {
        int r = idx / (DR / 2), i = idx % (DR / 2);
        const float* bq = &q[(size_t)(q0 + r) * QW + h * DQ + DN];
        float x1 = bq[2 * i], x2 = bq[2 * i + 1];
        rope_pair((float)(q0 + r), i, x1, x2);
        sQ[r * SQP + kperm(DN + 2 * i)]     = f2tf32(x1 * scale);
        sQ[r * SQP + kperm(DN + 2 * i + 1)] = f2tf32(x2 * scale);
    }

    float o[16][4] = {};
    float m_a = -1e30f, m_b = -1e30f, l_a = 0.f, l_b = 0.f;
    const int jt_end = 2 * bx + 1;

    for (int jt = 0; jt <= jt_end; jt++) {
        const int k0 = jt * ABN;

        CP_WAIT(0);        // K(jt) landed
        __syncthreads();   // K + (jt==0: Q) visible; prev sV/sP reads done

        issueV(k0);
        CP_COMMIT();

        // ---- S = Q @ K^T ----
        float s[8][4] = {};
        #pragma unroll 6
        for (int kb = 0; kb < DQ; kb += 8) {
            uint32_t a[4];
            uint2 aA = *reinterpret_cast<const uint2*>(&sQ[(r0 + gid) * SQP + kb + 2 * tig]);
            uint2 aB = *reinterpret_cast<const uint2*>(&sQ[(r0 + gid + 8) * SQP + kb + 2 * tig]);
            a[0] = aA.x; a[2] = aA.y; a[1] = aB.x; a[3] = aB.y;
            #pragma unroll
            for (int nt = 0; nt < 8; nt++) {
                uint32_t b[2];
                b[0] = sK[(nt * 8 + gid) * DKP + kb + tig];
                b[1] = sK[(nt * 8 + gid) * DKP + kb + tig + 4];
                mma_tf32(s[nt], a, b);
            }
        }
        __syncthreads();   // sK free

        if (jt < jt_end) {
            issueK(k0 + ABN);
            CP_COMMIT();
        }

        if (jt >= 2 * bx) {
            const int rowA = q0 + r0 + gid;
            const int rowB = rowA + 8;
            #pragma unroll
            for (int nt = 0; nt < 8; nt++) {
                int c0 = k0 + nt * 8 + tig * 2;
                if (c0 > rowA)     s[nt][0] = -1e30f;
                if (c0 + 1 > rowA) s[nt][1] = -1e30f;
                if (c0 > rowB)     s[nt][2] = -1e30f;
                if (c0 + 1 > rowB) s[nt][3] = -1e30f;
            }
        }

        float mxa = -1e30f, mxb = -1e30f;
        #pragma unroll
        for (int nt = 0; nt < 8; nt++) {
            mxa = fmaxf(mxa, fmaxf(s[nt][0], s[nt][1]));
            mxb = fmaxf(mxb, fmaxf(s[nt][2], s[nt][3]));
        }
        mxa = fmaxf(mxa, __shfl_xor_sync(~0u, mxa, 1));
        mxa = fmaxf(mxa, __shfl_xor_sync(~0u, mxa, 2));
        mxb = fmaxf(mxb, __shfl_xor_sync(~0u, mxb, 1));
        mxb = fmaxf(mxb, __shfl_xor_sync(~0u, mxb, 2));

        float mna = fmaxf(m_a, mxa), mnb = fmaxf(m_b, mxb);
        float alpha_a = __expf(m_a - mna), alpha_b = __expf(m_b - mnb);
        float sa = 0.f, sb = 0.f;
        #pragma unroll
        for (int nt = 0; nt < 8; nt++) {
            s[nt][0] = __expf(s[nt][0] - mna);
            s[nt][1] = __expf(s[nt][1] - mna);
            s[nt][2] = __expf(s[nt][2] - mnb);
            s[nt][3] = __expf(s[nt][3] - mnb);
            sa += s[nt][0] + s[nt][1];
            sb += s[nt][2] + s[nt][3];
        }
        sa += __shfl_xor_sync(~0u, sa, 1); sa += __shfl_xor_sync(~0u, sa, 2);
        sb += __shfl_xor_sync(~0u, sb, 1); sb += __shfl_xor_sync(~0u, sb, 2);
        l_a = l_a * alpha_a + sa;
        l_b = l_b * alpha_b + sb;
        m_a = mna; m_b = mnb;

        #pragma unroll
        for (int nt = 0; nt < 16; nt++) {
            o[nt][0] *= alpha_a; o[nt][1] *= alpha_a;
            o[nt][2] *= alpha_b; o[nt][3] *= alpha_b;
        }

        if (jt < jt_end) { CP_WAIT(1); } else { CP_WAIT(0); }
        __syncthreads();   // V visible

        // stash P (perm layout; each warp owns its rows)
        #pragma unroll
        for (int nt = 0; nt < 8; nt++) {
            int c0 = nt * 8 + tig * 2;
            sP[(r0 + gid) * BNP + kperm(c0)]         = f2tf32(s[nt][0]);
            sP[(r0 + gid) * BNP + kperm(c0 + 1)]     = f2tf32(s[nt][1]);
            sP[(r0 + gid + 8) * BNP + kperm(c0)]     = f2tf32(s[nt][2]);
            sP[(r0 + gid + 8) * BNP + kperm(c0 + 1)] = f2tf32(s[nt][3]);
        }
        __syncwarp();

        // ---- O += P @ V ----
        #pragma unroll
        for (int kb = 0; kb < ABN; kb += 8) {
            uint32_t a[4];
            uint2 pA = *reinterpret_cast<const uint2*>(&sP[(r0 + gid) * BNP + kb + 2 * tig]);
            uint2 pB = *reinterpret_cast<const uint2*>(&sP[(r0 + gid + 8) * BNP + kb + 2 * tig]);
            a[0] = pA.x; a[2] = pA.y; a[1] = pB.x; a[3] = pB.y;
            #pragma unroll
            for (int nt = 0; nt < 16; nt++) {
                uint32_t b[2];
                b[0] = sV[(kb + tig) * DVP + nt * 8 + gid];
                b[1] = sV[(kb + tig + 4) * DVP + nt * 8 + gid];
                mma_tf32(o[nt], a, b);
            }
        }
    }

    // epilogue: round to tf32 (g_attn feeds the out-GEMM raw)
    const float inv_a = 1.0f / l_a, inv_b = 1.0f / l_b;
    const int rowA = q0 + r0 + gid, rowB = rowA + 8;
    #pragma unroll
    for (int nt = 0; nt < 16; nt++) {
        int cc = h * DVV + nt * 8 + tig * 2;
        *reinterpret_cast<float2*>(&out[(size_t)rowA * (NH * DVV) + cc]) =
            make_float2(f2tf32f(o[nt][0] * inv_a), f2tf32f(o[nt][1] * inv_a));
        *reinterpret_cast<float2*>(&out[(size_t)rowB * (NH * DVV) + cc]) =
            make_float2(f2tf32f(o[nt][2] * inv_b), f2tf32f(o[nt][3] * inv_b));
    }
}

// ---------------- launch --------------------------------------------------------
extern "C" void kernel_launch(void* const* d_in, const int* in_sizes, int n_in,
                              void* d_out, int out_size)
{
    const float* hidden = (const float*)d_in[1];
    const float* w_q    = (const float*)d_in[2];
    const float* w_kv_a = (const float*)d_in[3];
    const float* ln_w   = (const float*)d_in[4];
    const float* w_kv_b = (const float*)d_in[5];
    const float* w_o    = (const float*)d_in[6];
    float* out = (float*)d_out;

    float *q_p, *lat_p, *kva_p, *kpe_p, *kv_p, *attn_p;
    float *hid_r, *wq_r, *wkva_r, *wkvb_r, *wo_r;
    cudaGetSymbolAddress((void**)&q_p,    g_q);
    cudaGetSymbolAddress((void**)&lat_p,  g_latent);
    cudaGetSymbolAddress((void**)&kva_p,  g_kva);
    cudaGetSymbolAddress((void**)&kpe_p,  g_kpe);
    cudaGetSymbolAddress((void**)&kv_p,   g_kv);
    cudaGetSymbolAddress((void**)&attn_p, g_attn);
    cudaGetSymbolAddress((void**)&hid_r,  g_hid_r);
    cudaGetSymbolAddress((void**)&wq_r,   g_wq_r);
    cudaGetSymbolAddress((void**)&wkva_r, g_wkva_r);
    cudaGetSymbolAddress((void**)&wkvb_r, g_wkvb_r);
    cudaGetSymbolAddress((void**)&wo_r,   g_wo_r);

    cudaFuncSetAttribute(gemm_tf32_dual,
                         cudaFuncAttributeMaxDynamicSharedMemorySize, GEMM_SMEM);
    cudaFuncSetAttribute(mla_attn_tc,
                         cudaFuncAttributeMaxDynamicSharedMemorySize, ATTN_SMEM);

    dim3 blk(256);

    // pre-round inputs
    {
        int n;
        n = TT * HIDDEN / 4;       round_copy<<<(n + 255) / 256, blk>>>(hidden, hid_r, n);
        n = HIDDEN * QW / 4;       round_copy<<<(n + 255) / 256, blk>>>(w_q, wq_r, n);
        n = HIDDEN * LATW / 4;     round_copy<<<(n + 255) / 256, blk>>>(w_kv_a, wkva_r, n);
        n = KV_LORA * KVW / 4;     round_copy<<<(n + 255) / 256, blk>>>(w_kv_b, wkvb_r, n);
        n = NH * DVV * HIDDEN / 4; round_copy<<<(n + 255) / 256, blk>>>(w_o, wo_r, n);
    }

    const int t1 = QW / 256;                 // 12
    const int t2 = (LATW + 255) / 256;       // 3

    // fused: q = hidden@w_q AND latent = hidden@w_kv_a
    gemm_tf32_dual<<<dim3(t1 + t2, TT / 128), blk, GEMM_SMEM>>>(
        hid_r, wq_r, q_p, QW, wkva_r, lat_p, LATW, HIDDEN, 0);
    // rmsnorm + rope_k fused
    rmsnorm_ropek_kernel<<<TT, 256>>>(lat_p, ln_w, kva_p, kpe_p);
    // kv = kva @ w_kv_b (rounded output feeds attention raw)
    gemm_tf32_dual<<<dim3(KVW / 256, TT / 128), blk, GEMM_SMEM>>>(
        kva_p, wkvb_r, kv_p, KVW, (const float*)nullptr, (float*)nullptr, 0, KV_LORA, 1);
    // attention (LPT; fused rope_q; rounds g_attn in epilogue)
    mla_attn_tc<<<(TT / ABM) * NH, blk, ATTN_SMEM>>>(q_p, kv_p, kpe_p, attn_p);
    // out = attn @ w_o
    gemm_tf32_dual<<<dim3(HIDDEN / 256, TT / 128), blk, GEMM_SMEM>>>(
        attn_p, wo_r, out, HIDDEN, (const float*)nullptr, (float*)nullptr, 0, NH * DVV, 0);
}

// round 11
// speedup vs baseline: 1.0386x; 1.0386x over previous
#include <cuda_runtime.h>
#include <cuda_bf16.h>
#include <cstdint>
#include <math.h>

#define TT 2048
#define HIDDEN 2048
#define NH 16
#define DN 128
#define DR 64
#define DVV 128
#define KV_LORA 512
#define DQ (DN + DR)          // 192
#define QW (NH * DQ)          // 3072
#define KVW (NH * (DN + DVV)) // 4096
#define LATW (KV_LORA + DR)   // 576

// ---------------- scratch ----------------------------------------------------
__device__ float g_q[TT * QW];
__device__ float g_latent[TT * LATW];
__device__ float g_kva[TT * KV_LORA];     // K-permuted (A of kv-GEMM)
__device__ float g_kpe[TT * DR];
__device__ float g_kv[TT * KVW];
__device__ float g_attn[TT * NH * DVV];   // K-permuted (A of out-GEMM)
__device__ float g_hid_r[TT * HIDDEN];    // rounded + K-permuted (A of qkv-GEMM)
__device__ float g_wq_r[HIDDEN * QW];
__device__ float g_wkva_r[HIDDEN * LATW];
__device__ float g_wkvb_r[KV_LORA * KVW];
__device__ float g_wo_r[NH * DVV * HIDDEN];

// ---------------- helpers -----------------------------------------------------
__device__ __forceinline__ uint32_t f2tf32(float x) {
    uint32_t r;
    asm("cvt.rna.tf32.f32 %0, %1;" : "=r"(r) : "f"(x));
    return r;
}
__device__ __forceinline__ float f2tf32f(float x) { return __uint_as_float(f2tf32(x)); }

__device__ __forceinline__ void mma_tf32(float c[4], const uint32_t a[4], const uint32_t b[2]) {
    asm volatile(
        "mma.sync.aligned.m16n8k8.row.col.f32.tf32.tf32.f32 "
        "{%0,%1,%2,%3}, {%4,%5,%6,%7}, {%8,%9}, {%0,%1,%2,%3};"
        : "+f"(c[0]), "+f"(c[1]), "+f"(c[2]), "+f"(c[3])
        : "r"(a[0]), "r"(a[1]), "r"(a[2]), "r"(a[3]), "r"(b[0]), "r"(b[1]));
}

__device__ __forceinline__ uint32_t smem_u32(const void* p) {
    return (uint32_t)__cvta_generic_to_shared(p);
}
__device__ __forceinline__ void cp16(uint32_t dst, const void* src, int src_bytes) {
    asm volatile("cp.async.cg.shared.global [%0], [%1], 16, %2;"
                 :: "r"(dst), "l"(src), "r"(src_bytes));
}
#define CP_COMMIT() asm volatile("cp.async.commit_group;")
#define CP_WAIT(n)  asm volatile("cp.async.wait_group %0;" :: "n"(n))

// K-dim permutation within 8-word groups: frag pairs (tig, tig+4) -> adjacent.
// Position kperm(d) holds logical k-index d.
__device__ __forceinline__ int kperm(int d) {
    return (d & ~7) + 2 * (d & 3) + ((d >> 2) & 1);
}

__device__ __forceinline__ void rope_pair(float p, int i, float& x1, float& x2) {
    float inv = 1.0f / powf(10000.0f, (float)(2 * i) / (float)DR);
    float f = p * inv;
    float c = cosf(f), s = sinf(f);
    float o1 = x1 * c - x2 * s;
    float o2 = x2 * c + x1 * s;
    x1 = o1; x2 = o2;
}

// ---------------- prep kernels ---------------------------------------------------
__global__ __launch_bounds__(256) void round_copy(
    const float* __restrict__ in, float* __restrict__ out, int n4)
{
    int i = blockIdx.x * 256 + threadIdx.x;
    if (i < n4) {
        float4 v = reinterpret_cast<const float4*>(in)[i];
        float4 o;
        o.x = f2tf32f(v.x); o.y = f2tf32f(v.y);
        o.z = f2tf32f(v.z); o.w = f2tf32f(v.w);
        reinterpret_cast<float4*>(out)[i] = o;
    }
}

// round + permute within 8-word groups: out[g + kperm(d)] = round(in[g + d])
__global__ __launch_bounds__(256) void round_permute_copy(
    const float* __restrict__ in, float* __restrict__ out, int n8)
{
    int i = blockIdx.x * 256 + threadIdx.x;
    if (i < n8) {
        float4 i0 = reinterpret_cast<const float4*>(in)[2 * i];      // v0..v3
        float4 i1 = reinterpret_cast<const float4*>(in)[2 * i + 1];  // v4..v7
        float4 o0, o1;
        o0.x = f2tf32f(i0.x); o0.y = f2tf32f(i1.x);  // pos0=v0, pos1=v4
        o0.z = f2tf32f(i0.y); o0.w = f2tf32f(i1.y);  // pos2=v1, pos3=v5
        o1.x = f2tf32f(i0.z); o1.y = f2tf32f(i1.z);  // pos4=v2, pos5=v6
        o1.z = f2tf32f(i0.w); o1.w = f2tf32f(i1.w);  // pos6=v3, pos7=v7
        reinterpret_cast<float4*>(out)[2 * i]     = o0;
        reinterpret_cast<float4*>(out)[2 * i + 1] = o1;
    }
}

// ---------------- TF32 GEMM: A pre-permuted in gmem, cp16 staging, v2 a-frags ----
#define GSTAGES 4
#define GA_STRIDE 40
#define GB_STRIDE 264
#define GAW (128 * GA_STRIDE)            // 5120 words
#define GBW (32 * GB_STRIDE)             // 8448 words
#define GSTAGE_W (GAW + GBW)             // 13568 words
#define GEMM_SMEM (GSTAGES * GSTAGE_W * 4)  // 217088 B

__global__ __launch_bounds__(256, 1) void gemm_tf32_dual(
    const float* __restrict__ A,
    const float* __restrict__ B1, float* __restrict__ C1, int N1,
    const float* __restrict__ B2, float* __restrict__ C2, int N2,
    int K, int roundC)
{
    extern __shared__ float gsm[];
    const uint32_t smBase = smem_u32(gsm);

    const int tiles1 = (N1 + 255) / 256;
    const float* B; float* C; int N, n0;
    if ((int)blockIdx.x < tiles1) {
        B = B1; C = C1; N = N1; n0 = blockIdx.x * 256;
    } else {
        B = B2; C = C2; N = N2; n0 = (blockIdx.x - tiles1) * 256;
    }

    const int tid  = threadIdx.x;
    const int lane = tid & 31, warp = tid >> 5;
    const int warpM = warp & 1;
    const int warpN = warp >> 1;
    const int gid = lane >> 2, tig = lane & 3;
    const int m0 = blockIdx.y * 128;

    const int ar = tid >> 3, ac = (tid & 7) * 4;   // A staging (contiguous 16B)
    const int br = tid >> 6, bc = (tid & 63) * 4;

    const int nslab = K >> 5;

    auto issue_slab = [&](int slab) {
        const int k0 = slab * 32;
        const uint32_t stg = smBase + (uint32_t)((slab & (GSTAGES - 1)) * GSTAGE_W) * 4;
        #pragma unroll
        for (int i = 0; i < 4; i++) {
            uint32_t dst = stg + (uint32_t)((ar + 32 * i) * GA_STRIDE + ac) * 4;
            cp16(dst, &A[(size_t)(m0 + ar + 32 * i) * K + k0 + ac], 16);
        }
        const int col = n0 + bc;
        const int ok = (col < N) ? 16 : 0;
        #pragma unroll
        for (int i = 0; i < 8; i++) {
            uint32_t dst = stg + (uint32_t)(GAW + (br + 4 * i) * GB_STRIDE + bc) * 4;
            cp16(dst, &B[(size_t)(k0 + br + 4 * i) * N + col], ok);
        }
    };

    #pragma unroll
    for (int s = 0; s < GSTAGES - 1; s++) {
        if (s < nslab) issue_slab(s);
        CP_COMMIT();
    }

    float c[4][8][4] = {};

    for (int i = 0; i < nslab; i++) {
        CP_WAIT(GSTAGES - 2);
        __syncthreads();

        if (i + GSTAGES - 1 < nslab) issue_slab(i + GSTAGES - 1);
        CP_COMMIT();

        const uint32_t* Ab = (const uint32_t*)(gsm + (i & (GSTAGES - 1)) * GSTAGE_W);
        const uint32_t* Bb = Ab + GAW;

        #pragma unroll
        for (int ks = 0; ks < 4; ks++) {
            const int kb = ks * 8;
            uint32_t a[4][4], b[8][2];
            #pragma unroll
            for (int mt = 0; mt < 4; mt++) {
                int r = warpM * 64 + mt * 16 + gid;
                uint2 aA = *reinterpret_cast<const uint2*>(&Ab[r * GA_STRIDE + kb + 2 * tig]);
                uint2 aB = *reinterpret_cast<const uint2*>(&Ab[(r + 8) * GA_STRIDE + kb + 2 * tig]);
                a[mt][0] = aA.x; a[mt][2] = aA.y;   // k=tig, k=tig+4
                a[mt][1] = aB.x; a[mt][3] = aB.y;
            }
            #pragma unroll
            for (int nt = 0; nt < 8; nt++) {
                int cc = warpN * 64 + nt * 8 + gid;
                b[nt][0] = Bb[(kb + tig) * GB_STRIDE + cc];
                b[nt][1] = Bb[(kb + tig + 4) * GB_STRIDE + cc];
            }
            #pragma unroll
            for (int mt = 0; mt < 4; mt++)
                #pragma unroll
                for (int nt = 0; nt < 8; nt++)
                    mma_tf32(c[mt][nt], a[mt], b[nt]);
        }
    }

    #pragma unroll
    for (int mt = 0; mt < 4; mt++) {
        #pragma unroll
        for (int nt = 0; nt < 8; nt++) {
            int r = m0 + warpM * 64 + mt * 16 + gid;
            int cc = n0 + warpN * 64 + nt * 8 + tig * 2;
            if (cc < N) {
                float v0 = c[mt][nt][0], v1 = c[mt][nt][1];
                float v2 = c[mt][nt][2], v3 = c[mt][nt][3];
                if (roundC) {
                    v0 = f2tf32f(v0); v1 = f2tf32f(v1);
                    v2 = f2tf32f(v2); v3 = f2tf32f(v3);
                }
                *reinterpret_cast<float2*>(&C[(size_t)r * N + cc]) = make_float2(v0, v1);
                *reinterpret_cast<float2*>(&C[(size_t)(r + 8) * N + cc]) = make_float2(v2, v3);
            }
        }
    }
}

// ---------------- rmsnorm + rope_k fused (kva written K-permuted) ----------------
__global__ __launch_bounds__(256) void rmsnorm_ropek_kernel(
    const float* __restrict__ latent, const float* __restrict__ w,
    float* __restrict__ out, float* __restrict__ kpe)
{
    const int t = blockIdx.x;
    const float* x = latent + (size_t)t * LATW;
    __shared__ float red[8];
    float ss = 0.f;
    for (int i = threadIdx.x; i < KV_LORA; i += 256) { float v = x[i]; ss += v * v; }
    #pragma unroll
    for (int o = 16; o > 0; o >>= 1) ss += __shfl_xor_sync(~0u, ss, o);
    if ((threadIdx.x & 31) == 0) red[threadIdx.x >> 5] = ss;
    __syncthreads();
    if (threadIdx.x == 0) {
        float v = 0.f;
        #pragma unroll
        for (int i = 0; i < 8; i++) v += red[i];
        red[0] = v;
    }
    __syncthreads();
    const float inv = rsqrtf(red[0] / (float)KV_LORA + 1e-6f);
    for (int i = threadIdx.x; i < KV_LORA; i += 256)
        out[(size_t)t * KV_LORA + kperm(i)] = f2tf32f(x[i] * inv * w[i]);

    if (threadIdx.x < DR / 2) {
        int i = threadIdx.x;
        float x1 = x[KV_LORA + 2 * i], x2 = x[KV_LORA + 2 * i + 1];
        rope_pair((float)t, i, x1, x2);
        kpe[(size_t)t * DR + 2 * i]     = f2tf32f(x1);
        kpe[(size_t)t * DR + 2 * i + 1] = f2tf32f(x2);
    }
}

// ---------------- tensor-core flash attention -------------------------------------
// sQ/sP permuted + v2 frag loads; sK/sV raw. Epilogue writes g_attn K-permuted.
#define ABM 128
#define ABN 64
#define SQP 200
#define DKP (DQ + 4)    // 196
#define DVP (DVV + 8)   // 136
#define BNP 72
#define SQ_W (ABM * SQP)
#define SK_W (ABN * DKP)
#define SV_W (ABN * DVP)
#define SP_W (ABM * BNP)
#define ATTN_SMEM ((SQ_W + SK_W + SV_W + SP_W) * 4)  // 224256 B

__global__ __launch_bounds__(256) void mla_attn_tc(
    const float* __restrict__ q, const float* __restrict__ kv,
    const float* __restrict__ kpe, float* __restrict__ out)
{
    extern __shared__ uint32_t asm_[];
    uint32_t* sQ = asm_;
    uint32_t* sK = asm_ + SQ_W;
    uint32_t* sV = asm_ + SQ_W + SK_W;
    uint32_t* sP = asm_ + SQ_W + SK_W + SV_W;
    const uint32_t sKb = smem_u32(sK);
    const uint32_t sVb = smem_u32(sV);

    const int bx = (TT / ABM - 1) - ((int)blockIdx.x >> 4);  // LPT order
    const int h  = (int)blockIdx.x & (NH - 1);
    const int q0 = bx * ABM;
    const int tid = threadIdx.x;
    const int lane = tid & 31, warp = tid >> 5;
    const int gid = lane >> 2, tig = lane & 3;
    const int r0 = warp * 16;
    const float scale = rsqrtf((float)DQ);

    auto issueK = [&](int k0) {
        #pragma unroll
        for (int j = 0; j < 12; j++) {
            int c = j * 256 + tid;
            int r = c / 48, col4 = (c % 48) * 4;
            uint32_t dst = sKb + (uint32_t)(r * DKP + col4) * 4;
            const float* src = (col4 < DN)
                ? &kv[(size_t)(k0 + r) * KVW + h * (DN + DVV) + col4]
                : &kpe[(size_t)(k0 + r) * DR + (col4 - DN)];
            cp16(dst, src, 16);
        }
    };
    auto issueV = [&](int k0) {
        #pragma unroll
        for (int j = 0; j < 8; j++) {
            int c = j * 256 + tid;
            int r = c / 32, col4 = (c % 32) * 4;
            uint32_t dst = sVb + (uint32_t)(r * DVP + col4) * 4;
            cp16(dst, &kv[(size_t)(k0 + r) * KVW + h * (DN + DVV) + DN + col4], 16);
        }
    };

    issueK(0);
    CP_COMMIT();

    for (int idx = tid; idx < ABM * DN; idx += 256) {
        int r = idx / DN, d = idx % DN;
        sQ[r * SQP + kperm(d)] = f2tf32(q[(size_t)(q0 + r) * QW + h * DQ + d] * scale);
    }
    for (int idx = tid; idx < ABM * (DR / 2); idx += 256) {
        int r = idx / (DR / 2), i = idx % (DR / 2);
        const float* bq = &q[(size_t)(q0 + r) * QW + h * DQ + DN];
        float x1 = bq[2 * i], x2 = bq[2 * i + 1];
        rope_pair((float)(q0 + r), i, x1, x2);
        sQ[r * SQP + kperm(DN + 2 * i)]     = f2tf32(x1 * scale);
        sQ[r * SQP + kperm(DN + 2 * i + 1)] = f2tf32(x2 * scale);
    }

    float o[16][4] = {};
    float m_a = -1e30f, m_b = -1e30f, l_a = 0.f, l_b = 0.f;
    const int jt_end = 2 * bx + 1;

    for (int jt = 0; jt <= jt_end; jt++) {
        const int k0 = jt * ABN;

        CP_WAIT(0);
        __syncthreads();

        issueV(k0);
        CP_COMMIT();

        float s[8][4] = {};
        #pragma unroll 6
        for (int kb = 0; kb < DQ; kb += 8) {
            uint32_t a[4];
            uint2 aA = *reinterpret_cast<const uint2*>(&sQ[(r0 + gid) * SQP + kb + 2 * tig]);
            uint2 aB = *reinterpret_cast<const uint2*>(&sQ[(r0 + gid + 8) * SQP + kb + 2 * tig]);
            a[0] = aA.x; a[2] = aA.y; a[1] = aB.x; a[3] = aB.y;
            #pragma unroll
            for (int nt = 0; nt < 8; nt++) {
                uint32_t b[2];
                b[0] = sK[(nt * 8 + gid) * DKP + kb + tig];
                b[1] = sK[(nt * 8 + gid) * DKP + kb + tig + 4];
                mma_tf32(s[nt], a, b);
            }
        }
        __syncthreads();

        if (jt < jt_end) {
            issueK(k0 + ABN);
            CP_COMMIT();
        }

        if (jt >= 2 * bx) {
            const int rowA = q0 + r0 + gid;
            const int rowB = rowA + 8;
            #pragma unroll
            for (int nt = 0; nt < 8; nt++) {
                int c0 = k0 + nt * 8 + tig * 2;
                if (c0 > rowA)     s[nt][0] = -1e30f;
                if (c0 + 1 > rowA) s[nt][1] = -1e30f;
                if (c0 > rowB)     s[nt][2] = -1e30f;
                if (c0 + 1 > rowB) s[nt][3] = -1e30f;
            }
        }

        float mxa = -1e30f, mxb = -1e30f;
        #pragma unroll
        for (int nt = 0; nt < 8; nt++) {
            mxa = fmaxf(mxa, fmaxf(s[nt][0], s[nt][1]));
            mxb = fmaxf(mxb, fmaxf(s[nt][2], s[nt][3]));
        }
        mxa = fmaxf(mxa, __shfl_xor_sync(~0u, mxa, 1));
        mxa = fmaxf(mxa, __shfl_xor_sync(~0u, mxa, 2));
        mxb = fmaxf(mxb, __shfl_xor_sync(~0u, mxb, 1));
        mxb = fmaxf(mxb, __shfl_xor_sync(~0u, mxb, 2));

        float mna = fmaxf(m_a, mxa), mnb = fmaxf(m_b, mxb);
        float alpha_a = __expf(m_a - mna), alpha_b = __expf(m_b - mnb);
        float sa = 0.f, sb = 0.f;
        #pragma unroll
        for (int nt = 0; nt < 8; nt++) {
            s[nt][0] = __expf(s[nt][0] - mna);
            s[nt][1] = __expf(s[nt][1] - mna);
            s[nt][2] = __expf(s[nt][2] - mnb);
            s[nt][3] = __expf(s[nt][3] - mnb);
            sa += s[nt][0] + s[nt][1];
            sb += s[nt][2] + s[nt][3];
        }
        sa += __shfl_xor_sync(~0u, sa, 1); sa += __shfl_xor_sync(~0u, sa, 2);
        sb += __shfl_xor_sync(~0u, sb, 1); sb += __shfl_xor_sync(~0u, sb, 2);
        l_a = l_a * alpha_a + sa;
        l_b = l_b * alpha_b + sb;
        m_a = mna; m_b = mnb;

        #pragma unroll
        for (int nt = 0; nt < 16; nt++) {
            o[nt][0] *= alpha_a; o[nt][1] *= alpha_a;
            o[nt][2] *= alpha_b; o[nt][3] *= alpha_b;
        }

        if (jt < jt_end) { CP_WAIT(1); } else { CP_WAIT(0); }
        __syncthreads();

        #pragma unroll
        for (int nt = 0; nt < 8; nt++) {
            int c0 = nt * 8 + tig * 2;
            sP[(r0 + gid) * BNP + kperm(c0)]         = f2tf32(s[nt][0]);
            sP[(r0 + gid) * BNP + kperm(c0 + 1)]     = f2tf32(s[nt][1]);
            sP[(r0 + gid + 8) * BNP + kperm(c0)]     = f2tf32(s[nt][2]);
            sP[(r0 + gid + 8) * BNP + kperm(c0 + 1)] = f2tf32(s[nt][3]);
        }
        __syncwarp();

        #pragma unroll
        for (int kb = 0; kb < ABN; kb += 8) {
            uint32_t a[4];
            uint2 pA = *reinterpret_cast<const uint2*>(&sP[(r0 + gid) * BNP + kb + 2 * tig]);
            uint2 pB = *reinterpret_cast<const uint2*>(&sP[(r0 + gid + 8) * BNP + kb + 2 * tig]);
            a[0] = pA.x; a[2] = pA.y; a[1] = pB.x; a[3] = pB.y;
            #pragma unroll
            for (int nt = 0; nt < 16; nt++) {
                uint32_t b[2];
                b[0] = sV[(kb + tig) * DVP + nt * 8 + gid];
                b[1] = sV[(kb + tig + 4) * DVP + nt * 8 + gid];
                mma_tf32(o[nt], a, b);
            }
        }
    }

    // epilogue: round + K-permute (g_attn is A of out-GEMM)
    const float inv_a = 1.0f / l_a, inv_b = 1.0f / l_b;
    const int rowA = q0 + r0 + gid, rowB = rowA + 8;
    #pragma unroll
    for (int nt = 0; nt < 16; nt++) {
        int cc = h * DVV + nt * 8 + tig * 2;
        int p0 = (cc & ~7) + kperm(cc & 7);
        int p1 = (cc & ~7) + kperm((cc & 7) + 1);
        out[(size_t)rowA * (NH * DVV) + p0] = f2tf32f(o[nt][0] * inv_a);
        out[(size_t)rowA * (NH * DVV) + p1] = f2tf32f(o[nt][1] * inv_a);
        out[(size_t)rowB * (NH * DVV) + p0] = f2tf32f(o[nt][2] * inv_b);
        out[(size_t)rowB * (NH * DVV) + p1] = f2tf32f(o[nt][3] * inv_b);
    }
}

// ---------------- launch --------------------------------------------------------
extern "C" void kernel_launch(void* const* d_in, const int* in_sizes, int n_in,
                              void* d_out, int out_size)
{
    const float* hidden = (const float*)d_in[1];
    const float* w_q    = (const float*)d_in[2];
    const float* w_kv_a = (const float*)d_in[3];
    const float* ln_w   = (const float*)d_in[4];
    const float* w_kv_b = (const float*)d_in[5];
    const float* w_o    = (const float*)d_in[6];
    float* out = (float*)d_out;

    float *q_p, *lat_p, *kva_p, *kpe_p, *kv_p, *attn_p;
    float *hid_r, *wq_r, *wkva_r, *wkvb_r, *wo_r;
    cudaGetSymbolAddress((void**)&q_p,    g_q);
    cudaGetSymbolAddress((void**)&lat_p,  g_latent);
    cudaGetSymbolAddress((void**)&kva_p,  g_kva);
    cudaGetSymbolAddress((void**)&kpe_p,  g_kpe);
    cudaGetSymbolAddress((void**)&kv_p,   g_kv);
    cudaGetSymbolAddress((void**)&attn_p, g_attn);
    cudaGetSymbolAddress((void**)&hid_r,  g_hid_r);
    cudaGetSymbolAddress((void**)&wq_r,   g_wq_r);
    cudaGetSymbolAddress((void**)&wkva_r, g_wkva_r);
    cudaGetSymbolAddress((void**)&wkvb_r, g_wkvb_r);
    cudaGetSymbolAddress((void**)&wo_r,   g_wo_r);

    cudaFuncSetAttribute(gemm_tf32_dual,
                         cudaFuncAttributeMaxDynamicSharedMemorySize, GEMM_SMEM);
    cudaFuncSetAttribute(mla_attn_tc,
                         cudaFuncAttributeMaxDynamicSharedMemorySize, ATTN_SMEM);

    dim3 blk(256);

    // prep: hidden rounded+permuted (GEMM A); weights rounded (GEMM B)
    {
        int n;
        n = TT * HIDDEN / 8;       round_permute_copy<<<(n + 255) / 256, blk>>>(hidden, hid_r, n);
        n = HIDDEN * QW / 4;       round_copy<<<(n + 255) / 256, blk>>>(w_q, wq_r, n);
        n = HIDDEN * LATW / 4;     round_copy<<<(n + 255) / 256, blk>>>(w_kv_a, wkva_r, n);
        n = KV_LORA * KVW / 4;     round_copy<<<(n + 255) / 256, blk>>>(w_kv_b, wkvb_r, n);
        n = NH * DVV * HIDDEN / 4; round_copy<<<(n + 255) / 256, blk>>>(w_o, wo_r, n);
    }

    const int t1 = QW / 256;                 // 12
    const int t2 = (LATW + 255) / 256;       // 3

    gemm_tf32_dual<<<dim3(t1 + t2, TT / 128), blk, GEMM_SMEM>>>(
        hid_r, wq_r, q_p, QW, wkva_r, lat_p, LATW, HIDDEN, 0);
    rmsnorm_ropek_kernel<<<TT, 256>>>(lat_p, ln_w, kva_p, kpe_p);
    gemm_tf32_dual<<<dim3(KVW / 256, TT / 128), blk, GEMM_SMEM>>>(
        kva_p, wkvb_r, kv_p, KVW, (const float*)nullptr, (float*)nullptr, 0, KV_LORA, 1);
    mla_attn_tc<<<(TT / ABM) * NH, blk, ATTN_SMEM>>>(q_p, kv_p, kpe_p, attn_p);
    gemm_tf32_dual<<<dim3(HIDDEN / 256, TT / 128), blk, GEMM_SMEM>>>(
        attn_p, wo_r, out, HIDDEN, (const float*)nullptr, (float*)nullptr, 0, NH * DVV, 0);
}

// round 12
// speedup vs baseline: 1.0683x; 1.0286x over previous
#include <cuda_runtime.h>
#include <cuda_bf16.h>
#include <cstdint>
#include <math.h>

#define TT 2048
#define HIDDEN 2048
#define NH 16
#define DN 128
#define DR 64
#define DVV 128
#define KV_LORA 512
#define DQ (DN + DR)          // 192
#define QW (NH * DQ)          // 3072
#define KVW (NH * (DN + DVV)) // 4096
#define LATW (KV_LORA + DR)   // 576

// ---------------- scratch ----------------------------------------------------
__device__ float g_q[TT * QW];
__device__ float g_latent[TT * LATW];
__device__ float g_kva[TT * KV_LORA];     // K-permuted (A of kv-GEMM)
__device__ float g_kpe[TT * DR];          // K-permuted (attention K cols 128..191)
__device__ float g_kv[TT * KVW];          // nope cols K-permuted, v cols raw
__device__ float g_attn[TT * NH * DVV];   // K-permuted (A of out-GEMM)
__device__ float g_hid_r[TT * HIDDEN];    // rounded + K-permuted (A of qkv-GEMM)
// transposed [n][k] + rounded + K-permuted weights (B operands)
__device__ float g_wqT[QW * HIDDEN];
__device__ float g_wkvaT[LATW * HIDDEN];
__device__ float g_wkvbT[KVW * KV_LORA];
__device__ float g_woT[HIDDEN * (NH * DVV)];

// ---------------- helpers -----------------------------------------------------
__device__ __forceinline__ uint32_t f2tf32(float x) {
    uint32_t r;
    asm("cvt.rna.tf32.f32 %0, %1;" : "=r"(r) : "f"(x));
    return r;
}
__device__ __forceinline__ float f2tf32f(float x) { return __uint_as_float(f2tf32(x)); }

__device__ __forceinline__ void mma_tf32(float c[4], const uint32_t a[4], const uint32_t b[2]) {
    asm volatile(
        "mma.sync.aligned.m16n8k8.row.col.f32.tf32.tf32.f32 "
        "{%0,%1,%2,%3}, {%4,%5,%6,%7}, {%8,%9}, {%0,%1,%2,%3};"
        : "+f"(c[0]), "+f"(c[1]), "+f"(c[2]), "+f"(c[3])
        : "r"(a[0]), "r"(a[1]), "r"(a[2]), "r"(a[3]), "r"(b[0]), "r"(b[1]));
}

__device__ __forceinline__ uint32_t smem_u32(const void* p) {
    return (uint32_t)__cvta_generic_to_shared(p);
}
__device__ __forceinline__ void cp16(uint32_t dst, const void* src, int src_bytes) {
    asm volatile("cp.async.cg.shared.global [%0], [%1], 16, %2;"
                 :: "r"(dst), "l"(src), "r"(src_bytes));
}
#define CP_COMMIT() asm volatile("cp.async.commit_group;")
#define CP_WAIT(n)  asm volatile("cp.async.wait_group %0;" :: "n"(n))

// K-dim permutation within 8-word groups: storage[kperm(d)] = value[d]
__device__ __forceinline__ int kperm(int d) {
    return (d & ~7) + 2 * (d & 3) + ((d >> 2) & 1);
}

__device__ __forceinline__ void rope_pair(float p, int i, float& x1, float& x2) {
    float inv = 1.0f / powf(10000.0f, (float)(2 * i) / (float)DR);
    float f = p * inv;
    float c = cosf(f), s = sinf(f);
    float o1 = x1 * c - x2 * s;
    float o2 = x2 * c + x1 * s;
    x1 = o1; x2 = o2;
}

// ---------------- prep kernels ---------------------------------------------------
// round + K-permute within 8-word groups (row-major A operands)
__global__ __launch_bounds__(256) void round_permute_copy(
    const float* __restrict__ in, float* __restrict__ out, int n8)
{
    int i = blockIdx.x * 256 + threadIdx.x;
    if (i < n8) {
        float4 i0 = reinterpret_cast<const float4*>(in)[2 * i];
        float4 i1 = reinterpret_cast<const float4*>(in)[2 * i + 1];
        float4 o0, o1;
        o0.x = f2tf32f(i0.x); o0.y = f2tf32f(i1.x);
        o0.z = f2tf32f(i0.y); o0.w = f2tf32f(i1.y);
        o1.x = f2tf32f(i0.z); o1.y = f2tf32f(i1.z);
        o1.z = f2tf32f(i0.w); o1.w = f2tf32f(i1.w);
        reinterpret_cast<float4*>(out)[2 * i]     = o0;
        reinterpret_cast<float4*>(out)[2 * i + 1] = o1;
    }
}

// in [R][C] -> out [C][R] rounded, out-k (the R dim) permuted within 8-groups
__global__ __launch_bounds__(256) void transpose_round_perm(
    const float* __restrict__ in, float* __restrict__ out, int R, int C)
{
    __shared__ float t[32][33];
    const int bc = blockIdx.x * 32, br = blockIdx.y * 32;
    const int tx = threadIdx.x & 31, ty = threadIdx.x >> 5;
    #pragma unroll
    for (int i = 0; i < 4; i++) {
        int r = ty + i * 8;
        t[r][tx] = in[(size_t)(br + r) * C + bc + tx];
    }
    __syncthreads();
    const int pcol = br + (tx & ~7) + kperm(tx & 7);
    #pragma unroll
    for (int i = 0; i < 4; i++) {
        int r = ty + i * 8;
        out[(size_t)(bc + r) * R + pcol] = f2tf32f(t[tx][r]);
    }
}

// ---------------- TF32 GEMM: A[m][kperm], B[n][kperm] in gmem, 3-stage ----------
#define GSTAGES 3
#define GA_STRIDE 40
#define GB_STRIDE 40
#define GAW (128 * GA_STRIDE)            // 5120 words
#define GBW (256 * GB_STRIDE)            // 10240 words
#define GSTAGE_W (GAW + GBW)             // 15360 words
#define GEMM_SMEM (GSTAGES * GSTAGE_W * 4)  // 184320 B

__global__ __launch_bounds__(256, 1) void gemm_tf32_dual(
    const float* __restrict__ A,
    const float* __restrict__ B1t, float* __restrict__ C1, int N1,
    const float* __restrict__ B2t, float* __restrict__ C2, int N2,
    int K, int roundMode)   // 0: raw fp32 out; 2: round + permute nope cols (kv)
{
    extern __shared__ float gsm[];
    const uint32_t smBase = smem_u32(gsm);

    const int tiles1 = (N1 + 255) / 256;
    const float* Bt; float* C; int N, n0;
    if ((int)blockIdx.x < tiles1) {
        Bt = B1t; C = C1; N = N1; n0 = blockIdx.x * 256;
    } else {
        Bt = B2t; C = C2; N = N2; n0 = (blockIdx.x - tiles1) * 256;
    }

    const int tid  = threadIdx.x;
    const int lane = tid & 31, warp = tid >> 5;
    const int warpM = warp & 1;
    const int warpN = warp >> 1;
    const int gid = lane >> 2, tig = lane & 3;
    const int m0 = blockIdx.y * 128;

    const int ar = tid >> 3, ac = (tid & 7) * 4;   // A: 4 cp16 (rows ar+32i)
    const int nslab = K >> 5;

    auto issue_slab = [&](int slab) {
        const int k0 = slab * 32;
        const uint32_t stg = smBase + (uint32_t)((slab % GSTAGES) * GSTAGE_W) * 4;
        #pragma unroll
        for (int i = 0; i < 4; i++) {
            uint32_t dst = stg + (uint32_t)((ar + 32 * i) * GA_STRIDE + ac) * 4;
            cp16(dst, &A[(size_t)(m0 + ar + 32 * i) * K + k0 + ac], 16);
        }
        // B: [n][k] — 8 cp16 over 256 n-rows
        #pragma unroll
        for (int i = 0; i < 8; i++) {
            int idx = i * 256 + tid;
            int r = idx >> 3, ch = (idx & 7) * 4;
            int gn = n0 + r;
            uint32_t dst = stg + (uint32_t)(GAW + r * GB_STRIDE + ch) * 4;
            cp16(dst, &Bt[(size_t)gn * K + k0 + ch], (gn < N) ? 16 : 0);
        }
    };

    issue_slab(0); CP_COMMIT();
    if (nslab > 1) issue_slab(1);
    CP_COMMIT();

    float c[4][8][4] = {};

    for (int i = 0; i < nslab; i++) {
        CP_WAIT(1);
        __syncthreads();

        if (i + 2 < nslab) issue_slab(i + 2);
        CP_COMMIT();

        const uint32_t* Ab = (const uint32_t*)(gsm + (i % GSTAGES) * GSTAGE_W);
        const uint32_t* Bb = Ab + GAW;

        #pragma unroll
        for (int ks = 0; ks < 4; ks++) {
            const int kb = ks * 8;
            uint32_t a[4][4], b[8][2];
            #pragma unroll
            for (int mt = 0; mt < 4; mt++) {
                int r = warpM * 64 + mt * 16 + gid;
                uint2 aA = *reinterpret_cast<const uint2*>(&Ab[r * GA_STRIDE + kb + 2 * tig]);
                uint2 aB = *reinterpret_cast<const uint2*>(&Ab[(r + 8) * GA_STRIDE + kb + 2 * tig]);
                a[mt][0] = aA.x; a[mt][2] = aA.y;
                a[mt][1] = aB.x; a[mt][3] = aB.y;
            }
            #pragma unroll
            for (int nt = 0; nt < 8; nt++) {
                int cc = warpN * 64 + nt * 8 + gid;
                uint2 bv = *reinterpret_cast<const uint2*>(&Bb[cc * GB_STRIDE + kb + 2 * tig]);
                b[nt][0] = bv.x; b[nt][1] = bv.y;
            }
            #pragma unroll
            for (int mt = 0; mt < 4; mt++)
                #pragma unroll
                for (int nt = 0; nt < 8; nt++)
                    mma_tf32(c[mt][nt], a[mt], b[nt]);
        }
    }

    #pragma unroll
    for (int mt = 0; mt < 4; mt++) {
        #pragma unroll
        for (int nt = 0; nt < 8; nt++) {
            int r = m0 + warpM * 64 + mt * 16 + gid;
            int cc = n0 + warpN * 64 + nt * 8 + tig * 2;
            if (cc < N) {
                float v0 = c[mt][nt][0], v1 = c[mt][nt][1];
                float v2 = c[mt][nt][2], v3 = c[mt][nt][3];
                if (roundMode == 2) {
                    // kv output: round; K-permute nope columns (per-head col<128)
                    v0 = f2tf32f(v0); v1 = f2tf32f(v1);
                    v2 = f2tf32f(v2); v3 = f2tf32f(v3);
                    int ch = cc & 255;
                    int p0 = cc, p1 = cc + 1;
                    if (ch < DN) {
                        p0 = (cc & ~7) + kperm(cc & 7);
                        p1 = (cc & ~7) + kperm((cc & 7) + 1);
                    }
                    C[(size_t)r * N + p0] = v0;
                    C[(size_t)r * N + p1] = v1;
                    C[(size_t)(r + 8) * N + p0] = v2;
                    C[(size_t)(r + 8) * N + p1] = v3;
                } else {
                    *reinterpret_cast<float2*>(&C[(size_t)r * N + cc]) = make_float2(v0, v1);
                    *reinterpret_cast<float2*>(&C[(size_t)(r + 8) * N + cc]) = make_float2(v2, v3);
                }
            }
        }
    }
}

// ---------------- rmsnorm + rope_k fused (kva, kpe written K-permuted) ----------
__global__ __launch_bounds__(256) void rmsnorm_ropek_kernel(
    const float* __restrict__ latent, const float* __restrict__ w,
    float* __restrict__ out, float* __restrict__ kpe)
{
    const int t = blockIdx.x;
    const float* x = latent + (size_t)t * LATW;
    __shared__ float red[8];
    float ss = 0.f;
    for (int i = threadIdx.x; i < KV_LORA; i += 256) { float v = x[i]; ss += v * v; }
    #pragma unroll
    for (int o = 16; o > 0; o >>= 1) ss += __shfl_xor_sync(~0u, ss, o);
    if ((threadIdx.x & 31) == 0) red[threadIdx.x >> 5] = ss;
    __syncthreads();
    if (threadIdx.x == 0) {
        float v = 0.f;
        #pragma unroll
        for (int i = 0; i < 8; i++) v += red[i];
        red[0] = v;
    }
    __syncthreads();
    const float inv = rsqrtf(red[0] / (float)KV_LORA + 1e-6f);
    for (int i = threadIdx.x; i < KV_LORA; i += 256)
        out[(size_t)t * KV_LORA + kperm(i)] = f2tf32f(x[i] * inv * w[i]);

    if (threadIdx.x < DR / 2) {
        int i = threadIdx.x;
        float x1 = x[KV_LORA + 2 * i], x2 = x[KV_LORA + 2 * i + 1];
        rope_pair((float)t, i, x1, x2);
        kpe[(size_t)t * DR + kperm(2 * i)]     = f2tf32f(x1);
        kpe[(size_t)t * DR + kperm(2 * i + 1)] = f2tf32f(x2);
    }
}

// ---------------- tensor-core flash attention -------------------------------------
// sQ/sK/sP permuted + v2 frag loads; sV raw. Epilogue writes g_attn K-permuted.
#define ABM 128
#define ABN 64
#define SQP 200
#define DKP 200         // sK stride (perm + v2 conflict-free)
#define DVP (DVV + 8)   // 136
#define BNP 72
#define SQ_W (ABM * SQP)   // 25600
#define SK_W (ABN * DKP)   // 12800
#define SV_W (ABN * DVP)   // 8704
#define SP_W (ABM * BNP)   // 9216
#define ATTN_SMEM ((SQ_W + SK_W + SV_W + SP_W) * 4)  // 225280 B

__global__ __launch_bounds__(256) void mla_attn_tc(
    const float* __restrict__ q, const float* __restrict__ kv,
    const float* __restrict__ kpe, float* __restrict__ out)
{
    extern __shared__ uint32_t asm_[];
    uint32_t* sQ = asm_;
    uint32_t* sK = asm_ + SQ_W;
    uint32_t* sV = asm_ + SQ_W + SK_W;
    uint32_t* sP = asm_ + SQ_W + SK_W + SV_W;
    const uint32_t sKb = smem_u32(sK);
    const uint32_t sVb = smem_u32(sV);

    const int bx = (TT / ABM - 1) - ((int)blockIdx.x >> 4);  // LPT order
    const int h  = (int)blockIdx.x & (NH - 1);
    const int q0 = bx * ABM;
    const int tid = threadIdx.x;
    const int lane = tid & 31, warp = tid >> 5;
    const int gid = lane >> 2, tig = lane & 3;
    const int r0 = warp * 16;
    const float scale = rsqrtf((float)DQ);

    auto issueK = [&](int k0) {
        #pragma unroll
        for (int j = 0; j < 12; j++) {
            int c = j * 256 + tid;
            int r = c / 48, col4 = (c % 48) * 4;
            uint32_t dst = sKb + (uint32_t)(r * DKP + col4) * 4;
            const float* src = (col4 < DN)
                ? &kv[(size_t)(k0 + r) * KVW + h * (DN + DVV) + col4]
                : &kpe[(size_t)(k0 + r) * DR + (col4 - DN)];
            cp16(dst, src, 16);
        }
    };
    auto issueV = [&](int k0) {
        #pragma unroll
        for (int j = 0; j < 8; j++) {
            int c = j * 256 + tid;
            int r = c / 32, col4 = (c % 32) * 4;
            uint32_t dst = sVb + (uint32_t)(r * DVP + col4) * 4;
            cp16(dst, &kv[(size_t)(k0 + r) * KVW + h * (DN + DVV) + DN + col4], 16);
        }
    };

    issueK(0);
    CP_COMMIT();

    for (int idx = tid; idx < ABM * DN; idx += 256) {
        int r = idx / DN, d = idx % DN;
        sQ[r * SQP + kperm(d)] = f2tf32(q[(size_t)(q0 + r) * QW + h * DQ + d] * scale);
    }
    for (int idx = tid; idx < ABM * (DR / 2); idx += 256) {
        int r = idx / (DR / 2), i = idx % (DR / 2);
        const float* bq = &q[(size_t)(q0 + r) * QW + h * DQ + DN];
        float x1 = bq[2 * i], x2 = bq[2 * i + 1];
        rope_pair((float)(q0 + r), i, x1, x2);
        sQ[r * SQP + kperm(DN + 2 * i)]     = f2tf32(x1 * scale);
        sQ[r * SQP + kperm(DN + 2 * i + 1)] = f2tf32(x2 * scale);
    }

    float o[16][4] = {};
    float m_a = -1e30f, m_b = -1e30f, l_a = 0.f, l_b = 0.f;
    const int jt_end = 2 * bx + 1;

    for (int jt = 0; jt <= jt_end; jt++) {
        const int k0 = jt * ABN;

        CP_WAIT(0);
        __syncthreads();

        issueV(k0);
        CP_COMMIT();

        float s[8][4] = {};
        #pragma unroll 6
        for (int kb = 0; kb < DQ; kb += 8) {
            uint32_t a[4];
            uint2 aA = *reinterpret_cast<const uint2*>(&sQ[(r0 + gid) * SQP + kb + 2 * tig]);
            uint2 aB = *reinterpret_cast<const uint2*>(&sQ[(r0 + gid + 8) * SQP + kb + 2 * tig]);
            a[0] = aA.x; a[2] = aA.y; a[1] = aB.x; a[3] = aB.y;
            #pragma unroll
            for (int nt = 0; nt < 8; nt++) {
                uint32_t b[2];
                uint2 bv = *reinterpret_cast<const uint2*>(&sK[(nt * 8 + gid) * DKP + kb + 2 * tig]);
                b[0] = bv.x; b[1] = bv.y;
                mma_tf32(s[nt], a, b);
            }
        }
        __syncthreads();

        if (jt < jt_end) {
            issueK(k0 + ABN);
            CP_COMMIT();
        }

        if (jt >= 2 * bx) {
            const int rowA = q0 + r0 + gid;
            const int rowB = rowA + 8;
            #pragma unroll
            for (int nt = 0; nt < 8; nt++) {
                int c0 = k0 + nt * 8 + tig * 2;
                if (c0 > rowA)     s[nt][0] = -1e30f;
                if (c0 + 1 > rowA) s[nt][1] = -1e30f;
                if (c0 > rowB)     s[nt][2] = -1e30f;
                if (c0 + 1 > rowB) s[nt][3] = -1e30f;
            }
        }

        float mxa = -1e30f, mxb = -1e30f;
        #pragma unroll
        for (int nt = 0; nt < 8; nt++) {
            mxa = fmaxf(mxa, fmaxf(s[nt][0], s[nt][1]));
            mxb = fmaxf(mxb, fmaxf(s[nt][2], s[nt][3]));
        }
        mxa = fmaxf(mxa, __shfl_xor_sync(~0u, mxa, 1));
        mxa = fmaxf(mxa, __shfl_xor_sync(~0u, mxa, 2));
        mxb = fmaxf(mxb, __shfl_xor_sync(~0u, mxb, 1));
        mxb = fmaxf(mxb, __shfl_xor_sync(~0u, mxb, 2));

        float mna = fmaxf(m_a, mxa), mnb = fmaxf(m_b, mxb);
        float alpha_a = __expf(m_a - mna), alpha_b = __expf(m_b - mnb);
        float sa = 0.f, sb = 0.f;
        #pragma unroll
        for (int nt = 0; nt < 8; nt++) {
            s[nt][0] = __expf(s[nt][0] - mna);
            s[nt][1] = __expf(s[nt][1] - mna);
            s[nt][2] = __expf(s[nt][2] - mnb);
            s[nt][3] = __expf(s[nt][3] - mnb);
            sa += s[nt][0] + s[nt][1];
            sb += s[nt][2] + s[nt][3];
        }
        sa += __shfl_xor_sync(~0u, sa, 1); sa += __shfl_xor_sync(~0u, sa, 2);
        sb += __shfl_xor_sync(~0u, sb, 1); sb += __shfl_xor_sync(~0u, sb, 2);
        l_a = l_a * alpha_a + sa;
        l_b = l_b * alpha_b + sb;
        m_a = mna; m_b = mnb;

        #pragma unroll
        for (int nt = 0; nt < 16; nt++) {
            o[nt][0] *= alpha_a; o[nt][1] *= alpha_a;
            o[nt][2] *= alpha_b; o[nt][3] *= alpha_b;
        }

        if (jt < jt_end) { CP_WAIT(1); } else { CP_WAIT(0); }
        __syncthreads();

        #pragma unroll
        for (int nt = 0; nt < 8; nt++) {
            int c0 = nt * 8 + tig * 2;
            sP[(r0 + gid) * BNP + kperm(c0)]         = f2tf32(s[nt][0]);
            sP[(r0 + gid) * BNP + kperm(c0 + 1)]     = f2tf32(s[nt][1]);
            sP[(r0 + gid + 8) * BNP + kperm(c0)]     = f2tf32(s[nt][2]);
            sP[(r0 + gid + 8) * BNP + kperm(c0 + 1)] = f2tf32(s[nt][3]);
        }
        __syncwarp();

        #pragma unroll
        for (int kb = 0; kb < ABN; kb += 8) {
            uint32_t a[4];
            uint2 pA = *reinterpret_cast<const uint2*>(&sP[(r0 + gid) * BNP + kb + 2 * tig]);
            uint2 pB = *reinterpret_cast<const uint2*>(&sP[(r0 + gid + 8) * BNP + kb + 2 * tig]);
            a[0] = pA.x; a[2] = pA.y; a[1] = pB.x; a[3] = pB.y;
            #pragma unroll
            for (int nt = 0; nt < 16; nt++) {
                uint32_t b[2];
                b[0] = sV[(kb + tig) * DVP + nt * 8 + gid];
                b[1] = sV[(kb + tig + 4) * DVP + nt * 8 + gid];
                mma_tf32(o[nt], a, b);
            }
        }
    }

    // epilogue: round + K-permute (g_attn is A of out-GEMM)
    const float inv_a = 1.0f / l_a, inv_b = 1.0f / l_b;
    const int rowA = q0 + r0 + gid, rowB = rowA + 8;
    #pragma unroll
    for (int nt = 0; nt < 16; nt++) {
        int cc = h * DVV + nt * 8 + tig * 2;
        int p0 = (cc & ~7) + kperm(cc & 7);
        int p1 = (cc & ~7) + kperm((cc & 7) + 1);
        out[(size_t)rowA * (NH * DVV) + p0] = f2tf32f(o[nt][0] * inv_a);
        out[(size_t)rowA * (NH * DVV) + p1] = f2tf32f(o[nt][1] * inv_a);
        out[(size_t)rowB * (NH * DVV) + p0] = f2tf32f(o[nt][2] * inv_b);
        out[(size_t)rowB * (NH * DVV) + p1] = f2tf32f(o[nt][3] * inv_b);
    }
}

// ---------------- launch --------------------------------------------------------
extern "C" void kernel_launch(void* const* d_in, const int* in_sizes, int n_in,
                              void* d_out, int out_size)
{
    const float* hidden = (const float*)d_in[1];
    const float* w_q    = (const float*)d_in[2];
    const float* w_kv_a = (const float*)d_in[3];
    const float* ln_w   = (const float*)d_in[4];
    const float* w_kv_b = (const float*)d_in[5];
    const float* w_o    = (const float*)d_in[6];
    float* out = (float*)d_out;

    float *q_p, *lat_p, *kva_p, *kpe_p, *kv_p, *attn_p;
    float *hid_r, *wqT, *wkvaT, *wkvbT, *woT;
    cudaGetSymbolAddress((void**)&q_p,    g_q);
    cudaGetSymbolAddress((void**)&lat_p,  g_latent);
    cudaGetSymbolAddress((void**)&kva_p,  g_kva);
    cudaGetSymbolAddress((void**)&kpe_p,  g_kpe);
    cudaGetSymbolAddress((void**)&kv_p,   g_kv);
    cudaGetSymbolAddress((void**)&attn_p, g_attn);
    cudaGetSymbolAddress((void**)&hid_r,  g_hid_r);
    cudaGetSymbolAddress((void**)&wqT,    g_wqT);
    cudaGetSymbolAddress((void**)&wkvaT,  g_wkvaT);
    cudaGetSymbolAddress((void**)&wkvbT,  g_wkvbT);
    cudaGetSymbolAddress((void**)&woT,    g_woT);

    cudaFuncSetAttribute(gemm_tf32_dual,
                         cudaFuncAttributeMaxDynamicSharedMemorySize, GEMM_SMEM);
    cudaFuncSetAttribute(mla_attn_tc,
                         cudaFuncAttributeMaxDynamicSharedMemorySize, ATTN_SMEM);

    dim3 blk(256);

    // prep: hidden rounded+permuted (A); weights transposed+rounded+permuted (B)
    {
        int n = TT * HIDDEN / 8;
        round_permute_copy<<<(n + 255) / 256, blk>>>(hidden, hid_r, n);
        transpose_round_perm<<<dim3(QW / 32, HIDDEN / 32), blk>>>(w_q, wqT, HIDDEN, QW);
        transpose_round_perm<<<dim3(LATW / 32, HIDDEN / 32), blk>>>(w_kv_a, wkvaT, HIDDEN, LATW);
        transpose_round_perm<<<dim3(KVW / 32, KV_LORA / 32), blk>>>(w_kv_b, wkvbT, KV_LORA, KVW);
        transpose_round_perm<<<dim3(HIDDEN / 32, (NH * DVV) / 32), blk>>>(w_o, woT, NH * DVV, HIDDEN);
    }

    const int t1 = QW / 256;                 // 12
    const int t2 = (LATW + 255) / 256;       // 3

    gemm_tf32_dual<<<dim3(t1 + t2, TT / 128), blk, GEMM_SMEM>>>(
        hid_r, wqT, q_p, QW, wkvaT, lat_p, LATW, HIDDEN, 0);
    rmsnorm_ropek_kernel<<<TT, 256>>>(lat_p, ln_w, kva_p, kpe_p);
    gemm_tf32_dual<<<dim3(KVW / 256, TT / 128), blk, GEMM_SMEM>>>(
        kva_p, wkvbT, kv_p, KVW, (const float*)nullptr, (float*)nullptr, 0, KV_LORA, 2);
    mla_attn_tc<<<(TT / ABM) * NH, blk, ATTN_SMEM>>>(q_p, kv_p, kpe_p, attn_p);
    gemm_tf32_dual<<<dim3(HIDDEN / 256, TT / 128), blk, GEMM_SMEM>>>(
        attn_p, woT, out, HIDDEN, (const float*)nullptr, (float*)nullptr, 0, NH * DVV, 0);
}

// round 13
// speedup vs baseline: 1.0706x; 1.0021x over previous
#include <cuda_runtime.h>
#include <cuda_bf16.h>
#include <cstdint>
#include <math.h>

#define TT 2048
#define HIDDEN 2048
#define NH 16
#define DN 128
#define DR 64
#define DVV 128
#define KV_LORA 512
#define DQ (DN + DR)          // 192
#define QW (NH * DQ)          // 3072
#define KVW (NH * (DN + DVV)) // 4096
#define LATW (KV_LORA + DR)   // 576

// ---------------- scratch ----------------------------------------------------
__device__ float g_q[TT * QW];
__device__ float g_latent[TT * LATW];
__device__ float g_kva[TT * KV_LORA];     // K-permuted (A of kv-GEMM)
__device__ float g_kpe[TT * DR];          // K-permuted (attention K cols 128..191)
__device__ float g_kv[TT * KVW];          // nope cols K-permuted, v cols raw
__device__ float g_attn[TT * NH * DVV];   // K-permuted (A of out-GEMM)
__device__ float g_hid_r[TT * HIDDEN];    // rounded + K-permuted (A of qkv-GEMM)
// transposed [n][k] + rounded + K-permuted weights (B operands)
__device__ float g_wqT[QW * HIDDEN];
__device__ float g_wkvaT[LATW * HIDDEN];
__device__ float g_wkvbT[KVW * KV_LORA];
__device__ float g_woT[HIDDEN * (NH * DVV)];

// ---------------- helpers -----------------------------------------------------
__device__ __forceinline__ uint32_t f2tf32(float x) {
    uint32_t r;
    asm("cvt.rna.tf32.f32 %0, %1;" : "=r"(r) : "f"(x));
    return r;
}
__device__ __forceinline__ float f2tf32f(float x) { return __uint_as_float(f2tf32(x)); }

__device__ __forceinline__ void mma_tf32(float c[4], const uint32_t a[4], const uint32_t b[2]) {
    asm volatile(
        "mma.sync.aligned.m16n8k8.row.col.f32.tf32.tf32.f32 "
        "{%0,%1,%2,%3}, {%4,%5,%6,%7}, {%8,%9}, {%0,%1,%2,%3};"
        : "+f"(c[0]), "+f"(c[1]), "+f"(c[2]), "+f"(c[3])
        : "r"(a[0]), "r"(a[1]), "r"(a[2]), "r"(a[3]), "r"(b[0]), "r"(b[1]));
}

__device__ __forceinline__ uint32_t smem_u32(const void* p) {
    return (uint32_t)__cvta_generic_to_shared(p);
}
__device__ __forceinline__ void cp16(uint32_t dst, const void* src, int src_bytes) {
    asm volatile("cp.async.cg.shared.global [%0], [%1], 16, %2;"
                 :: "r"(dst), "l"(src), "r"(src_bytes));
}
#define CP_COMMIT() asm volatile("cp.async.commit_group;")
#define CP_WAIT(n)  asm volatile("cp.async.wait_group %0;" :: "n"(n))

// K-dim permutation within 8-word groups: storage[kperm(d)] = value[d]
__device__ __forceinline__ int kperm(int d) {
    return (d & ~7) + 2 * (d & 3) + ((d >> 2) & 1);
}

__device__ __forceinline__ void rope_pair(float p, int i, float& x1, float& x2) {
    float inv = 1.0f / powf(10000.0f, (float)(2 * i) / (float)DR);
    float f = p * inv;
    float c = cosf(f), s = sinf(f);
    float o1 = x1 * c - x2 * s;
    float o2 = x2 * c + x1 * s;
    x1 = o1; x2 = o2;
}

// ---------------- prep kernels ---------------------------------------------------
// round + K-permute within 8-word groups (row-major A operands)
__global__ __launch_bounds__(256) void round_permute_copy(
    const float* __restrict__ in, float* __restrict__ out, int n8)
{
    int i = blockIdx.x * 256 + threadIdx.x;
    if (i < n8) {
        float4 i0 = reinterpret_cast<const float4*>(in)[2 * i];
        float4 i1 = reinterpret_cast<const float4*>(in)[2 * i + 1];
        float4 o0, o1;
        o0.x = f2tf32f(i0.x); o0.y = f2tf32f(i1.x);
        o0.z = f2tf32f(i0.y); o0.w = f2tf32f(i1.y);
        o1.x = f2tf32f(i0.z); o1.y = f2tf32f(i1.z);
        o1.z = f2tf32f(i0.w); o1.w = f2tf32f(i1.w);
        reinterpret_cast<float4*>(out)[2 * i]     = o0;
        reinterpret_cast<float4*>(out)[2 * i + 1] = o1;
    }
}

// in [R][C] -> out [C][R] rounded, out-k (the R dim) permuted within 8-groups
__global__ __launch_bounds__(256) void transpose_round_perm(
    const float* __restrict__ in, float* __restrict__ out, int R, int C)
{
    __shared__ float t[32][33];
    const int bc = blockIdx.x * 32, br = blockIdx.y * 32;
    const int tx = threadIdx.x & 31, ty = threadIdx.x >> 5;
    #pragma unroll
    for (int i = 0; i < 4; i++) {
        int r = ty + i * 8;
        t[r][tx] = in[(size_t)(br + r) * C + bc + tx];
    }
    __syncthreads();
    const int pcol = br + (tx & ~7) + kperm(tx & 7);
    #pragma unroll
    for (int i = 0; i < 4; i++) {
        int r = ty + i * 8;
        out[(size_t)(bc + r) * R + pcol] = f2tf32f(t[tx][r]);
    }
}

// ---------------- TF32 GEMM: A[m][kperm], B[n][kperm] in gmem, 3-stage ----------
#define GSTAGES 3
#define GA_STRIDE 40
#define GB_STRIDE 40
#define GAW (128 * GA_STRIDE)            // 5120 words
#define GBW (256 * GB_STRIDE)            // 10240 words
#define GSTAGE_W (GAW + GBW)             // 15360 words
#define GEMM_SMEM (GSTAGES * GSTAGE_W * 4)  // 184320 B

__global__ __launch_bounds__(256, 1) void gemm_tf32_dual(
    const float* __restrict__ A,
    const float* __restrict__ B1t, float* __restrict__ C1, int N1,
    const float* __restrict__ B2t, float* __restrict__ C2, int N2,
    int K, int roundMode)   // 0: raw fp32 out; 2: round + permute nope cols (kv)
{
    extern __shared__ float gsm[];
    const uint32_t smBase = smem_u32(gsm);

    const int tiles1 = (N1 + 255) / 256;
    const float* Bt; float* C; int N, n0;
    if ((int)blockIdx.x < tiles1) {
        Bt = B1t; C = C1; N = N1; n0 = blockIdx.x * 256;
    } else {
        Bt = B2t; C = C2; N = N2; n0 = (blockIdx.x - tiles1) * 256;
    }

    const int tid  = threadIdx.x;
    const int lane = tid & 31, warp = tid >> 5;
    const int warpM = warp & 1;
    const int warpN = warp >> 1;
    const int gid = lane >> 2, tig = lane & 3;
    const int m0 = blockIdx.y * 128;

    const int ar = tid >> 3, ac = (tid & 7) * 4;   // A: 4 cp16 (rows ar+32i)
    const int nslab = K >> 5;

    auto issue_slab = [&](int slab) {
        const int k0 = slab * 32;
        const uint32_t stg = smBase + (uint32_t)((slab % GSTAGES) * GSTAGE_W) * 4;
        #pragma unroll
        for (int i = 0; i < 4; i++) {
            uint32_t dst = stg + (uint32_t)((ar + 32 * i) * GA_STRIDE + ac) * 4;
            cp16(dst, &A[(size_t)(m0 + ar + 32 * i) * K + k0 + ac], 16);
        }
        // B: [n][k] — 8 cp16 over 256 n-rows
        #pragma unroll
        for (int i = 0; i < 8; i++) {
            int idx = i * 256 + tid;
            int r = idx >> 3, ch = (idx & 7) * 4;
            int gn = n0 + r;
            uint32_t dst = stg + (uint32_t)(GAW + r * GB_STRIDE + ch) * 4;
            cp16(dst, &Bt[(size_t)gn * K + k0 + ch], (gn < N) ? 16 : 0);
        }
    };

    issue_slab(0); CP_COMMIT();
    if (nslab > 1) issue_slab(1);
    CP_COMMIT();

    float c[4][8][4] = {};

    for (int i = 0; i < nslab; i++) {
        CP_WAIT(1);
        __syncthreads();

        if (i + 2 < nslab) issue_slab(i + 2);
        CP_COMMIT();

        const uint32_t* Ab = (const uint32_t*)(gsm + (i % GSTAGES) * GSTAGE_W);
        const uint32_t* Bb = Ab + GAW;

        #pragma unroll
        for (int ks = 0; ks < 4; ks++) {
            const int kb = ks * 8;
            uint32_t a[4][4], b[8][2];
            #pragma unroll
            for (int mt = 0; mt < 4; mt++) {
                int r = warpM * 64 + mt * 16 + gid;
                uint2 aA = *reinterpret_cast<const uint2*>(&Ab[r * GA_STRIDE + kb + 2 * tig]);
                uint2 aB = *reinterpret_cast<const uint2*>(&Ab[(r + 8) * GA_STRIDE + kb + 2 * tig]);
                a[mt][0] = aA.x; a[mt][2] = aA.y;
                a[mt][1] = aB.x; a[mt][3] = aB.y;
            }
            #pragma unroll
            for (int nt = 0; nt < 8; nt++) {
                int cc = warpN * 64 + nt * 8 + gid;
                uint2 bv = *reinterpret_cast<const uint2*>(&Bb[cc * GB_STRIDE + kb + 2 * tig]);
                b[nt][0] = bv.x; b[nt][1] = bv.y;
            }
            #pragma unroll
            for (int mt = 0; mt < 4; mt++)
                #pragma unroll
                for (int nt = 0; nt < 8; nt++)
                    mma_tf32(c[mt][nt], a[mt], b[nt]);
        }
    }

    #pragma unroll
    for (int mt = 0; mt < 4; mt++) {
        #pragma unroll
        for (int nt = 0; nt < 8; nt++) {
            int r = m0 + warpM * 64 + mt * 16 + gid;
            int cc = n0 + warpN * 64 + nt * 8 + tig * 2;
            if (cc < N) {
                float v0 = c[mt][nt][0], v1 = c[mt][nt][1];
                float v2 = c[mt][nt][2], v3 = c[mt][nt][3];
                if (roundMode == 2) {
                    // kv output: round; K-permute nope columns (per-head col<128)
                    v0 = f2tf32f(v0); v1 = f2tf32f(v1);
                    v2 = f2tf32f(v2); v3 = f2tf32f(v3);
                    int ch = cc & 255;
                    int p0 = cc, p1 = cc + 1;
                    if (ch < DN) {
                        p0 = (cc & ~7) + kperm(cc & 7);
                        p1 = (cc & ~7) + kperm((cc & 7) + 1);
                    }
                    C[(size_t)r * N + p0] = v0;
                    C[(size_t)r * N + p1] = v1;
                    C[(size_t)(r + 8) * N + p0] = v2;
                    C[(size_t)(r + 8) * N + p1] = v3;
                } else {
                    *reinterpret_cast<float2*>(&C[(size_t)r * N + cc]) = make_float2(v0, v1);
                    *reinterpret_cast<float2*>(&C[(size_t)(r + 8) * N + cc]) = make_float2(v2, v3);
                }
            }
        }
    }
}

// ---------------- rmsnorm + rope_k fused (kva, kpe written K-permuted) ----------
__global__ __launch_bounds__(256) void rmsnorm_ropek_kernel(
    const float* __restrict__ latent, const float* __restrict__ w,
    float* __restrict__ out, float* __restrict__ kpe)
{
    const int t = blockIdx.x;
    const float* x = latent + (size_t)t * LATW;
    __shared__ float red[8];
    float ss = 0.f;
    for (int i = threadIdx.x; i < KV_LORA; i += 256) { float v = x[i]; ss += v * v; }
    #pragma unroll
    for (int o = 16; o > 0; o >>= 1) ss += __shfl_xor_sync(~0u, ss, o);
    if ((threadIdx.x & 31) == 0) red[threadIdx.x >> 5] = ss;
    __syncthreads();
    if (threadIdx.x == 0) {
        float v = 0.f;
        #pragma unroll
        for (int i = 0; i < 8; i++) v += red[i];
        red[0] = v;
    }
    __syncthreads();
    const float inv = rsqrtf(red[0] / (float)KV_LORA + 1e-6f);
    for (int i = threadIdx.x; i < KV_LORA; i += 256)
        out[(size_t)t * KV_LORA + kperm(i)] = f2tf32f(x[i] * inv * w[i]);

    if (threadIdx.x < DR / 2) {
        int i = threadIdx.x;
        float x1 = x[KV_LORA + 2 * i], x2 = x[KV_LORA + 2 * i + 1];
        rope_pair((float)t, i, x1, x2);
        kpe[(size_t)t * DR + kperm(2 * i)]     = f2tf32f(x1);
        kpe[(size_t)t * DR + kperm(2 * i + 1)] = f2tf32f(x2);
    }
}

// ---------------- tensor-core flash attention -------------------------------------
// sQ/sK/sP permuted + v2 frag loads; sV raw. Epilogue writes g_attn K-permuted.
#define ABM 128
#define ABN 64
#define SQP 200
#define DKP 200         // sK stride (perm + v2 conflict-free)
#define DVP (DVV + 8)   // 136
#define BNP 72
#define SQ_W (ABM * SQP)   // 25600
#define SK_W (ABN * DKP)   // 12800
#define SV_W (ABN * DVP)   // 8704
#define SP_W (ABM * BNP)   // 9216
#define ATTN_SMEM ((SQ_W + SK_W + SV_W + SP_W) * 4)  // 225280 B

__global__ __launch_bounds__(256) void mla_attn_tc(
    const float* __restrict__ q, const float* __restrict__ kv,
    const float* __restrict__ kpe, float* __restrict__ out)
{
    extern __shared__ uint32_t asm_[];
    uint32_t* sQ = asm_;
    uint32_t* sK = asm_ + SQ_W;
    uint32_t* sV = asm_ + SQ_W + SK_W;
    uint32_t* sP = asm_ + SQ_W + SK_W + SV_W;
    const uint32_t sKb = smem_u32(sK);
    const uint32_t sVb = smem_u32(sV);

    const int bx = (TT / ABM - 1) - ((int)blockIdx.x >> 4);  // LPT order
    const int h  = (int)blockIdx.x & (NH - 1);
    const int q0 = bx * ABM;
    const int tid = threadIdx.x;
    const int lane = tid & 31, warp = tid >> 5;
    const int gid = lane >> 2, tig = lane & 3;
    const int r0 = warp * 16;
    const float scale = rsqrtf((float)DQ);

    auto issueK = [&](int k0) {
        #pragma unroll
        for (int j = 0; j < 12; j++) {
            int c = j * 256 + tid;
            int r = c / 48, col4 = (c % 48) * 4;
            uint32_t dst = sKb + (uint32_t)(r * DKP + col4) * 4;
            const float* src = (col4 < DN)
                ? &kv[(size_t)(k0 + r) * KVW + h * (DN + DVV) + col4]
                : &kpe[(size_t)(k0 + r) * DR + (col4 - DN)];
            cp16(dst, src, 16);
        }
    };
    auto issueV = [&](int k0) {
        #pragma unroll
        for (int j = 0; j < 8; j++) {
            int c = j * 256 + tid;
            int r = c / 32, col4 = (c % 32) * 4;
            uint32_t dst = sVb + (uint32_t)(r * DVP + col4) * 4;
            cp16(dst, &kv[(size_t)(k0 + r) * KVW + h * (DN + DVV) + DN + col4], 16);
        }
    };

    issueK(0);
    CP_COMMIT();

    for (int idx = tid; idx < ABM * DN; idx += 256) {
        int r = idx / DN, d = idx % DN;
        sQ[r * SQP + kperm(d)] = f2tf32(q[(size_t)(q0 + r) * QW + h * DQ + d] * scale);
    }
    for (int idx = tid; idx < ABM * (DR / 2); idx += 256) {
        int r = idx / (DR / 2), i = idx % (DR / 2);
        const float* bq = &q[(size_t)(q0 + r) * QW + h * DQ + DN];
        float x1 = bq[2 * i], x2 = bq[2 * i + 1];
        rope_pair((float)(q0 + r), i, x1, x2);
        sQ[r * SQP + kperm(DN + 2 * i)]     = f2tf32(x1 * scale);
        sQ[r * SQP + kperm(DN + 2 * i + 1)] = f2tf32(x2 * scale);
    }

    float o[16][4] = {};
    float m_a = -1e30f, m_b = -1e30f, l_a = 0.f, l_b = 0.f;
    const int jt_end = 2 * bx + 1;

    for (int jt = 0; jt <= jt_end; jt++) {
        const int k0 = jt * ABN;

        CP_WAIT(0);
        __syncthreads();

        issueV(k0);
        CP_COMMIT();

        float s[8][4] = {};
        #pragma unroll 6
        for (int kb = 0; kb < DQ; kb += 8) {
            uint32_t a[4];
            uint2 aA = *reinterpret_cast<const uint2*>(&sQ[(r0 + gid) * SQP + kb + 2 * tig]);
            uint2 aB = *reinterpret_cast<const uint2*>(&sQ[(r0 + gid + 8) * SQP + kb + 2 * tig]);
            a[0] = aA.x; a[2] = aA.y; a[1] = aB.x; a[3] = aB.y;
            #pragma unroll
            for (int nt = 0; nt < 8; nt++) {
                uint32_t b[2];
                uint2 bv = *reinterpret_cast<const uint2*>(&sK[(nt * 8 + gid) * DKP + kb + 2 * tig]);
                b[0] = bv.x; b[1] = bv.y;
                mma_tf32(s[nt], a, b);
            }
        }
        __syncthreads();

        if (jt < jt_end) {
            issueK(k0 + ABN);
            CP_COMMIT();
        }

        if (jt >= 2 * bx) {
            const int rowA = q0 + r0 + gid;
            const int rowB = rowA + 8;
            #pragma unroll
            for (int nt = 0; nt < 8; nt++) {
                int c0 = k0 + nt * 8 + tig * 2;
                if (c0 > rowA)     s[nt][0] = -1e30f;
                if (c0 + 1 > rowA) s[nt][1] = -1e30f;
                if (c0 > rowB)     s[nt][2] = -1e30f;
                if (c0 + 1 > rowB) s[nt][3] = -1e30f;
            }
        }

        float mxa = -1e30f, mxb = -1e30f;
        #pragma unroll
        for (int nt = 0; nt < 8; nt++) {
            mxa = fmaxf(mxa, fmaxf(s[nt][0], s[nt][1]));
            mxb = fmaxf(mxb, fmaxf(s[nt][2], s[nt][3]));
        }
        mxa = fmaxf(mxa, __shfl_xor_sync(~0u, mxa, 1));
        mxa = fmaxf(mxa, __shfl_xor_sync(~0u, mxa, 2));
        mxb = fmaxf(mxb, __shfl_xor_sync(~0u, mxb, 1));
        mxb = fmaxf(mxb, __shfl_xor_sync(~0u, mxb, 2));

        float mna = fmaxf(m_a, mxa), mnb = fmaxf(m_b, mxb);
        float alpha_a = __expf(m_a - mna), alpha_b = __expf(m_b - mnb);
        float sa = 0.f, sb = 0.f;
        #pragma unroll
        for (int nt = 0; nt < 8; nt++) {
            s[nt][0] = __expf(s[nt][0] - mna);
            s[nt][1] = __expf(s[nt][1] - mna);
            s[nt][2] = __expf(s[nt][2] - mnb);
            s[nt][3] = __expf(s[nt][3] - mnb);
            sa += s[nt][0] + s[nt][1];
            sb += s[nt][2] + s[nt][3];
        }
        sa += __shfl_xor_sync(~0u, sa, 1); sa += __shfl_xor_sync(~0u, sa, 2);
        sb += __shfl_xor_sync(~0u, sb, 1); sb += __shfl_xor_sync(~0u, sb, 2);
        l_a = l_a * alpha_a + sa;
        l_b = l_b * alpha_b + sb;
        m_a = mna; m_b = mnb;

        #pragma unroll
        for (int nt = 0; nt < 16; nt++) {
            o[nt][0] *= alpha_a; o[nt][1] *= alpha_a;
            o[nt][2] *= alpha_b; o[nt][3] *= alpha_b;
        }

        if (jt < jt_end) { CP_WAIT(1); } else { CP_WAIT(0); }
        __syncthreads();

        #pragma unroll
        for (int nt = 0; nt < 8; nt++) {
            int c0 = nt * 8 + tig * 2;
            sP[(r0 + gid) * BNP + kperm(c0)]         = f2tf32(s[nt][0]);
            sP[(r0 + gid) * BNP + kperm(c0 + 1)]     = f2tf32(s[nt][1]);
            sP[(r0 + gid + 8) * BNP + kperm(c0)]     = f2tf32(s[nt][2]);
            sP[(r0 + gid + 8) * BNP + kperm(c0 + 1)] = f2tf32(s[nt][3]);
        }
        __syncwarp();

        #pragma unroll
        for (int kb = 0; kb < ABN; kb += 8) {
            uint32_t a[4];
            uint2 pA = *reinterpret_cast<const uint2*>(&sP[(r0 + gid) * BNP + kb + 2 * tig]);
            uint2 pB = *reinterpret_cast<const uint2*>(&sP[(r0 + gid + 8) * BNP + kb + 2 * tig]);
            a[0] = pA.x; a[2] = pA.y; a[1] = pB.x; a[3] = pB.y;
            #pragma unroll
            for (int nt = 0; nt < 16; nt++) {
                uint32_t b[2];
                b[0] = sV[(kb + tig) * DVP + nt * 8 + gid];
                b[1] = sV[(kb + tig + 4) * DVP + nt * 8 + gid];
                mma_tf32(o[nt], a, b);
            }
        }
    }

    // epilogue: round + K-permute (g_attn is A of out-GEMM)
    const float inv_a = 1.0f / l_a, inv_b = 1.0f / l_b;
    const int rowA = q0 + r0 + gid, rowB = rowA + 8;
    #pragma unroll
    for (int nt = 0; nt < 16; nt++) {
        int cc = h * DVV + nt * 8 + tig * 2;
        int p0 = (cc & ~7) + kperm(cc & 7);
        int p1 = (cc & ~7) + kperm((cc & 7) + 1);
        out[(size_t)rowA * (NH * DVV) + p0] = f2tf32f(o[nt][0] * inv_a);
        out[(size_t)rowA * (NH * DVV) + p1] = f2tf32f(o[nt][1] * inv_a);
        out[(size_t)rowB * (NH * DVV) + p0] = f2tf32f(o[nt][2] * inv_b);
        out[(size_t)rowB * (NH * DVV) + p1] = f2tf32f(o[nt][3] * inv_b);
    }
}

// ---------------- launch --------------------------------------------------------
extern "C" void kernel_launch(void* const* d_in, const int* in_sizes, int n_in,
                              void* d_out, int out_size)
{
    const float* hidden = (const float*)d_in[1];
    const float* w_q    = (const float*)d_in[2];
    const float* w_kv_a = (const float*)d_in[3];
    const float* ln_w   = (const float*)d_in[4];
    const float* w_kv_b = (const float*)d_in[5];
    const float* w_o    = (const float*)d_in[6];
    float* out = (float*)d_out;

    float *q_p, *lat_p, *kva_p, *kpe_p, *kv_p, *attn_p;
    float *hid_r, *wqT, *wkvaT, *wkvbT, *woT;
    cudaGetSymbolAddress((void**)&q_p,    g_q);
    cudaGetSymbolAddress((void**)&lat_p,  g_latent);
    cudaGetSymbolAddress((void**)&kva_p,  g_kva);
    cudaGetSymbolAddress((void**)&kpe_p,  g_kpe);
    cudaGetSymbolAddress((void**)&kv_p,   g_kv);
    cudaGetSymbolAddress((void**)&attn_p, g_attn);
    cudaGetSymbolAddress((void**)&hid_r,  g_hid_r);
    cudaGetSymbolAddress((void**)&wqT,    g_wqT);
    cudaGetSymbolAddress((void**)&wkvaT,  g_wkvaT);
    cudaGetSymbolAddress((void**)&wkvbT,  g_wkvbT);
    cudaGetSymbolAddress((void**)&woT,    g_woT);

    cudaFuncSetAttribute(gemm_tf32_dual,
                         cudaFuncAttributeMaxDynamicSharedMemorySize, GEMM_SMEM);
    cudaFuncSetAttribute(mla_attn_tc,
                         cudaFuncAttributeMaxDynamicSharedMemorySize, ATTN_SMEM);

    dim3 blk(256);

    // prep: hidden rounded+permuted (A); weights transposed+rounded+permuted (B)
    {
        int n = TT * HIDDEN / 8;
        round_permute_copy<<<(n + 255) / 256, blk>>>(hidden, hid_r, n);
        transpose_round_perm<<<dim3(QW / 32, HIDDEN / 32), blk>>>(w_q, wqT, HIDDEN, QW);
        transpose_round_perm<<<dim3(LATW / 32, HIDDEN / 32), blk>>>(w_kv_a, wkvaT, HIDDEN, LATW);
        transpose_round_perm<<<dim3(KVW / 32, KV_LORA / 32), blk>>>(w_kv_b, wkvbT, KV_LORA, KVW);
        transpose_round_perm<<<dim3(HIDDEN / 32, (NH * DVV) / 32), blk>>>(w_o, woT, NH * DVV, HIDDEN);
    }

    const int t1 = QW / 256;                 // 12
    const int t2 = (LATW + 255) / 256;       // 3

    gemm_tf32_dual<<<dim3(t1 + t2, TT / 128), blk, GEMM_SMEM>>>(
        hid_r, wqT, q_p, QW, wkvaT, lat_p, LATW, HIDDEN, 0);
    rmsnorm_ropek_kernel<<<TT, 256>>>(lat_p, ln_w, kva_p, kpe_p);
    gemm_tf32_dual<<<dim3(KVW / 256, TT / 128), blk, GEMM_SMEM>>>(
        kva_p, wkvbT, kv_p, KVW, (const float*)nullptr, (float*)nullptr, 0, KV_LORA, 2);
    mla_attn_tc<<<(TT / ABM) * NH, blk, ATTN_SMEM>>>(q_p, kv_p, kpe_p, attn_p);
    gemm_tf32_dual<<<dim3(HIDDEN / 256, TT / 128), blk, GEMM_SMEM>>>(
        attn_p, woT, out, HIDDEN, (const float*)nullptr, (float*)nullptr, 0, NH * DVV, 0);
}

// round 14
// speedup vs baseline: 1.0724x; 1.0016x over previous
#include <cuda_runtime.h>
#include <cuda_bf16.h>
#include <cstdint>
#include <math.h>

#define TT 2048
#define HIDDEN 2048
#define NH 16
#define DN 128
#define DR 64
#define DVV 128
#define KV_LORA 512
#define DQ (DN + DR)          // 192
#define QW (NH * DQ)          // 3072
#define KVW (NH * (DN + DVV)) // 4096
#define LATW (KV_LORA + DR)   // 576

// ---------------- scratch ----------------------------------------------------
__device__ float g_q[TT * QW];
__device__ float g_latent[TT * LATW];
__device__ float g_kva[TT * KV_LORA];     // K-permuted (A of kv-GEMM)
__device__ float g_kpe[TT * DR];          // K-permuted (attention K cols 128..191)
__device__ float g_kv[TT * KVW];          // nope cols K-permuted, v cols raw
__device__ float g_attn[TT * NH * DVV];   // K-permuted (A of out-GEMM)
__device__ float g_hid_r[TT * HIDDEN];    // rounded + K-permuted (A of qkv-GEMM)
// transposed [n][k] + rounded + K-permuted weights (B operands)
__device__ float g_wqT[QW * HIDDEN];
__device__ float g_wkvaT[LATW * HIDDEN];
__device__ float g_wkvbT[KVW * KV_LORA];
__device__ float g_woT[HIDDEN * (NH * DVV)];

// ---------------- helpers -----------------------------------------------------
__device__ __forceinline__ uint32_t f2tf32(float x) {
    uint32_t r;
    asm("cvt.rna.tf32.f32 %0, %1;" : "=r"(r) : "f"(x));
    return r;
}
__device__ __forceinline__ float f2tf32f(float x) { return __uint_as_float(f2tf32(x)); }

__device__ __forceinline__ void mma_tf32(float c[4], const uint32_t a[4], const uint32_t b[2]) {
    asm volatile(
        "mma.sync.aligned.m16n8k8.row.col.f32.tf32.tf32.f32 "
        "{%0,%1,%2,%3}, {%4,%5,%6,%7}, {%8,%9}, {%0,%1,%2,%3};"
        : "+f"(c[0]), "+f"(c[1]), "+f"(c[2]), "+f"(c[3])
        : "r"(a[0]), "r"(a[1]), "r"(a[2]), "r"(a[3]), "r"(b[0]), "r"(b[1]));
}

__device__ __forceinline__ uint32_t smem_u32(const void* p) {
    return (uint32_t)__cvta_generic_to_shared(p);
}
__device__ __forceinline__ void cp16(uint32_t dst, const void* src, int src_bytes) {
    asm volatile("cp.async.cg.shared.global [%0], [%1], 16, %2;"
                 :: "r"(dst), "l"(src), "r"(src_bytes));
}
#define CP_COMMIT() asm volatile("cp.async.commit_group;")
#define CP_WAIT(n)  asm volatile("cp.async.wait_group %0;" :: "n"(n))

// K-dim permutation within 8-word groups: storage[kperm(d)] = value[d]
__device__ __forceinline__ int kperm(int d) {
    return (d & ~7) + 2 * (d & 3) + ((d >> 2) & 1);
}

__device__ __forceinline__ void rope_pair(float p, int i, float& x1, float& x2) {
    float inv = 1.0f / powf(10000.0f, (float)(2 * i) / (float)DR);
    float f = p * inv;
    float c = cosf(f), s = sinf(f);
    float o1 = x1 * c - x2 * s;
    float o2 = x2 * c + x1 * s;
    x1 = o1; x2 = o2;
}

// ---------------- prep kernels ---------------------------------------------------
// round + K-permute within 8-word groups (row-major A operands)
__global__ __launch_bounds__(256) void round_permute_copy(
    const float* __restrict__ in, float* __restrict__ out, int n8)
{
    int i = blockIdx.x * 256 + threadIdx.x;
    if (i < n8) {
        float4 i0 = reinterpret_cast<const float4*>(in)[2 * i];
        float4 i1 = reinterpret_cast<const float4*>(in)[2 * i + 1];
        float4 o0, o1;
        o0.x = f2tf32f(i0.x); o0.y = f2tf32f(i1.x);
        o0.z = f2tf32f(i0.y); o0.w = f2tf32f(i1.y);
        o1.x = f2tf32f(i0.z); o1.y = f2tf32f(i1.z);
        o1.z = f2tf32f(i0.w); o1.w = f2tf32f(i1.w);
        reinterpret_cast<float4*>(out)[2 * i]     = o0;
        reinterpret_cast<float4*>(out)[2 * i + 1] = o1;
    }
}

// in [R][C] -> out [C][R] rounded, out-k (the R dim) permuted within 8-groups
__global__ __launch_bounds__(256) void transpose_round_perm(
    const float* __restrict__ in, float* __restrict__ out, int R, int C)
{
    __shared__ float t[32][33];
    const int bc = blockIdx.x * 32, br = blockIdx.y * 32;
    const int tx = threadIdx.x & 31, ty = threadIdx.x >> 5;
    #pragma unroll
    for (int i = 0; i < 4; i++) {
        int r = ty + i * 8;
        t[r][tx] = in[(size_t)(br + r) * C + bc + tx];
    }
    __syncthreads();
    const int pcol = br + (tx & ~7) + kperm(tx & 7);
    #pragma unroll
    for (int i = 0; i < 4; i++) {
        int r = ty + i * 8;
        out[(size_t)(bc + r) * R + pcol] = f2tf32f(t[tx][r]);
    }
}

// ---------------- TF32 GEMM: A[m][kperm], B[n][kperm] in gmem, 3-stage ----------
#define GSTAGES 3
#define GA_STRIDE 40
#define GB_STRIDE 40
#define GAW (128 * GA_STRIDE)            // 5120 words
#define GBW (256 * GB_STRIDE)            // 10240 words
#define GSTAGE_W (GAW + GBW)             // 15360 words
#define GEMM_SMEM (GSTAGES * GSTAGE_W * 4)  // 184320 B

__global__ __launch_bounds__(256, 1) void gemm_tf32_dual(
    const float* __restrict__ A,
    const float* __restrict__ B1t, float* __restrict__ C1, int N1,
    const float* __restrict__ B2t, float* __restrict__ C2, int N2,
    int K, int roundMode)   // 0: raw fp32 out; 2: round + permute nope cols (kv)
{
    extern __shared__ float gsm[];
    const uint32_t smBase = smem_u32(gsm);

    const int tiles1 = (N1 + 255) / 256;
    const float* Bt; float* C; int N, n0;
    if ((int)blockIdx.x < tiles1) {
        Bt = B1t; C = C1; N = N1; n0 = blockIdx.x * 256;
    } else {
        Bt = B2t; C = C2; N = N2; n0 = (blockIdx.x - tiles1) * 256;
    }

    const int tid  = threadIdx.x;
    const int lane = tid & 31, warp = tid >> 5;
    const int warpM = warp & 1;
    const int warpN = warp >> 1;
    const int gid = lane >> 2, tig = lane & 3;
    const int m0 = blockIdx.y * 128;

    const int ar = tid >> 3, ac = (tid & 7) * 4;   // A: 4 cp16 (rows ar+32i)
    const int nslab = K >> 5;

    auto issue_slab = [&](int slab) {
        const int k0 = slab * 32;
        const uint32_t stg = smBase + (uint32_t)((slab % GSTAGES) * GSTAGE_W) * 4;
        #pragma unroll
        for (int i = 0; i < 4; i++) {
            uint32_t dst = stg + (uint32_t)((ar + 32 * i) * GA_STRIDE + ac) * 4;
            cp16(dst, &A[(size_t)(m0 + ar + 32 * i) * K + k0 + ac], 16);
        }
        // B: [n][k] — 8 cp16 over 256 n-rows
        #pragma unroll
        for (int i = 0; i < 8; i++) {
            int idx = i * 256 + tid;
            int r = idx >> 3, ch = (idx & 7) * 4;
            int gn = n0 + r;
            uint32_t dst = stg + (uint32_t)(GAW + r * GB_STRIDE + ch) * 4;
            cp16(dst, &Bt[(size_t)gn * K + k0 + ch], (gn < N) ? 16 : 0);
        }
    };

    issue_slab(0); CP_COMMIT();
    if (nslab > 1) issue_slab(1);
    CP_COMMIT();

    float c[4][8][4] = {};

    for (int i = 0; i < nslab; i++) {
        CP_WAIT(1);
        __syncthreads();

        if (i + 2 < nslab) issue_slab(i + 2);
        CP_COMMIT();

        const uint32_t* Ab = (const uint32_t*)(gsm + (i % GSTAGES) * GSTAGE_W);
        const uint32_t* Bb = Ab + GAW;

        #pragma unroll
        for (int ks = 0; ks < 4; ks++) {
            const int kb = ks * 8;
            uint32_t a[4][4], b[8][2];
            #pragma unroll
            for (int mt = 0; mt < 4; mt++) {
                int r = warpM * 64 + mt * 16 + gid;
                uint2 aA = *reinterpret_cast<const uint2*>(&Ab[r * GA_STRIDE + kb + 2 * tig]);
                uint2 aB = *reinterpret_cast<const uint2*>(&Ab[(r + 8) * GA_STRIDE + kb + 2 * tig]);
                a[mt][0] = aA.x; a[mt][2] = aA.y;
                a[mt][1] = aB.x; a[mt][3] = aB.y;
            }
            #pragma unroll
            for (int nt = 0; nt < 8; nt++) {
                int cc = warpN * 64 + nt * 8 + gid;
                uint2 bv = *reinterpret_cast<const uint2*>(&Bb[cc * GB_STRIDE + kb + 2 * tig]);
                b[nt][0] = bv.x; b[nt][1] = bv.y;
            }
            #pragma unroll
            for (int mt = 0; mt < 4; mt++)
                #pragma unroll
                for (int nt = 0; nt < 8; nt++)
                    mma_tf32(c[mt][nt], a[mt], b[nt]);
        }
    }

    #pragma unroll
    for (int mt = 0; mt < 4; mt++) {
        #pragma unroll
        for (int nt = 0; nt < 8; nt++) {
            int r = m0 + warpM * 64 + mt * 16 + gid;
            int cc = n0 + warpN * 64 + nt * 8 + tig * 2;
            if (cc < N) {
                float v0 = c[mt][nt][0], v1 = c[mt][nt][1];
                float v2 = c[mt][nt][2], v3 = c[mt][nt][3];
                if (roundMode == 2) {
                    // kv output: round; K-permute nope columns (per-head col<128)
                    v0 = f2tf32f(v0); v1 = f2tf32f(v1);
                    v2 = f2tf32f(v2); v3 = f2tf32f(v3);
                    int ch = cc & 255;
                    int p0 = cc, p1 = cc + 1;
                    if (ch < DN) {
                        p0 = (cc & ~7) + kperm(cc & 7);
                        p1 = (cc & ~7) + kperm((cc & 7) + 1);
                    }
                    C[(size_t)r * N + p0] = v0;
                    C[(size_t)r * N + p1] = v1;
                    C[(size_t)(r + 8) * N + p0] = v2;
                    C[(size_t)(r + 8) * N + p1] = v3;
                } else {
                    *reinterpret_cast<float2*>(&C[(size_t)r * N + cc]) = make_float2(v0, v1);
                    *reinterpret_cast<float2*>(&C[(size_t)(r + 8) * N + cc]) = make_float2(v2, v3);
                }
            }
        }
    }
}

// ---------------- rmsnorm + rope_k fused (kva, kpe written K-permuted) ----------
__global__ __launch_bounds__(256) void rmsnorm_ropek_kernel(
    const float* __restrict__ latent, const float* __restrict__ w,
    float* __restrict__ out, float* __restrict__ kpe)
{
    const int t = blockIdx.x;
    const float* x = latent + (size_t)t * LATW;
    __shared__ float red[8];
    float ss = 0.f;
    for (int i = threadIdx.x; i < KV_LORA; i += 256) { float v = x[i]; ss += v * v; }
    #pragma unroll
    for (int o = 16; o > 0; o >>= 1) ss += __shfl_xor_sync(~0u, ss, o);
    if ((threadIdx.x & 31) == 0) red[threadIdx.x >> 5] = ss;
    __syncthreads();
    if (threadIdx.x == 0) {
        float v = 0.f;
        #pragma unroll
        for (int i = 0; i < 8; i++) v += red[i];
        red[0] = v;
    }
    __syncthreads();
    const float inv = rsqrtf(red[0] / (float)KV_LORA + 1e-6f);
    for (int i = threadIdx.x; i < KV_LORA; i += 256)
        out[(size_t)t * KV_LORA + kperm(i)] = f2tf32f(x[i] * inv * w[i]);

    if (threadIdx.x < DR / 2) {
        int i = threadIdx.x;
        float x1 = x[KV_LORA + 2 * i], x2 = x[KV_LORA + 2 * i + 1];
        rope_pair((float)t, i, x1, x2);
        kpe[(size_t)t * DR + kperm(2 * i)]     = f2tf32f(x1);
        kpe[(size_t)t * DR + kperm(2 * i + 1)] = f2tf32f(x2);
    }
}

// ---------------- tensor-core flash attention -------------------------------------
// sQ/sK/sP permuted + v2 frag loads; sV raw. Epilogue writes g_attn K-permuted.
#define ABM 128
#define ABN 64
#define SQP 200
#define DKP 200         // sK stride (perm + v2 conflict-free)
#define DVP (DVV + 8)   // 136
#define BNP 72
#define SQ_W (ABM * SQP)   // 25600
#define SK_W (ABN * DKP)   // 12800
#define SV_W (ABN * DVP)   // 8704
#define SP_W (ABM * BNP)   // 9216
#define ATTN_SMEM ((SQ_W + SK_W + SV_W + SP_W) * 4)  // 225280 B

__global__ __launch_bounds__(256) void mla_attn_tc(
    const float* __restrict__ q, const float* __restrict__ kv,
    const float* __restrict__ kpe, float* __restrict__ out)
{
    extern __shared__ uint32_t asm_[];
    uint32_t* sQ = asm_;
    uint32_t* sK = asm_ + SQ_W;
    uint32_t* sV = asm_ + SQ_W + SK_W;
    uint32_t* sP = asm_ + SQ_W + SK_W + SV_W;
    const uint32_t sKb = smem_u32(sK);
    const uint32_t sVb = smem_u32(sV);

    const int bx = (TT / ABM - 1) - ((int)blockIdx.x >> 4);  // LPT order
    const int h  = (int)blockIdx.x & (NH - 1);
    const int q0 = bx * ABM;
    const int tid = threadIdx.x;
    const int lane = tid & 31, warp = tid >> 5;
    const int gid = lane >> 2, tig = lane & 3;
    const int r0 = warp * 16;
    const float scale = rsqrtf((float)DQ);

    auto issueK = [&](int k0) {
        #pragma unroll
        for (int j = 0; j < 12; j++) {
            int c = j * 256 + tid;
            int r = c / 48, col4 = (c % 48) * 4;
            uint32_t dst = sKb + (uint32_t)(r * DKP + col4) * 4;
            const float* src = (col4 < DN)
                ? &kv[(size_t)(k0 + r) * KVW + h * (DN + DVV) + col4]
                : &kpe[(size_t)(k0 + r) * DR + (col4 - DN)];
            cp16(dst, src, 16);
        }
    };
    auto issueV = [&](int k0) {
        #pragma unroll
        for (int j = 0; j < 8; j++) {
            int c = j * 256 + tid;
            int r = c / 32, col4 = (c % 32) * 4;
            uint32_t dst = sVb + (uint32_t)(r * DVP + col4) * 4;
            cp16(dst, &kv[(size_t)(k0 + r) * KVW + h * (DN + DVV) + DN + col4], 16);
        }
    };

    issueK(0);
    CP_COMMIT();

    for (int idx = tid; idx < ABM * DN; idx += 256) {
        int r = idx / DN, d = idx % DN;
        sQ[r * SQP + kperm(d)] = f2tf32(q[(size_t)(q0 + r) * QW + h * DQ + d] * scale);
    }
    for (int idx = tid; idx < ABM * (DR / 2); idx += 256) {
        int r = idx / (DR / 2), i = idx % (DR / 2);
        const float* bq = &q[(size_t)(q0 + r) * QW + h * DQ + DN];
        float x1 = bq[2 * i], x2 = bq[2 * i + 1];
        rope_pair((float)(q0 + r), i, x1, x2);
        sQ[r * SQP + kperm(DN + 2 * i)]     = f2tf32(x1 * scale);
        sQ[r * SQP + kperm(DN + 2 * i + 1)] = f2tf32(x2 * scale);
    }

    float o[16][4] = {};
    float m_a = -1e30f, m_b = -1e30f, l_a = 0.f, l_b = 0.f;
    const int jt_end = 2 * bx + 1;

    for (int jt = 0; jt <= jt_end; jt++) {
        const int k0 = jt * ABN;

        CP_WAIT(0);
        __syncthreads();

        issueV(k0);
        CP_COMMIT();

        float s[8][4] = {};
        #pragma unroll 6
        for (int kb = 0; kb < DQ; kb += 8) {
            uint32_t a[4];
            uint2 aA = *reinterpret_cast<const uint2*>(&sQ[(r0 + gid) * SQP + kb + 2 * tig]);
            uint2 aB = *reinterpret_cast<const uint2*>(&sQ[(r0 + gid + 8) * SQP + kb + 2 * tig]);
            a[0] = aA.x; a[2] = aA.y; a[1] = aB.x; a[3] = aB.y;
            #pragma unroll
            for (int nt = 0; nt < 8; nt++) {
                uint32_t b[2];
                uint2 bv = *reinterpret_cast<const uint2*>(&sK[(nt * 8 + gid) * DKP + kb + 2 * tig]);
                b[0] = bv.x; b[1] = bv.y;
                mma_tf32(s[nt], a, b);
            }
        }
        __syncthreads();

        if (jt < jt_end) {
            issueK(k0 + ABN);
            CP_COMMIT();
        }

        if (jt >= 2 * bx) {
            const int rowA = q0 + r0 + gid;
            const int rowB = rowA + 8;
            #pragma unroll
            for (int nt = 0; nt < 8; nt++) {
                int c0 = k0 + nt * 8 + tig * 2;
                if (c0 > rowA)     s[nt][0] = -1e30f;
                if (c0 + 1 > rowA) s[nt][1] = -1e30f;
                if (c0 > rowB)     s[nt][2] = -1e30f;
                if (c0 + 1 > rowB) s[nt][3] = -1e30f;
            }
        }

        float mxa = -1e30f, mxb = -1e30f;
        #pragma unroll
        for (int nt = 0; nt < 8; nt++) {
            mxa = fmaxf(mxa, fmaxf(s[nt][0], s[nt][1]));
            mxb = fmaxf(mxb, fmaxf(s[nt][2], s[nt][3]));
        }
        mxa = fmaxf(mxa, __shfl_xor_sync(~0u, mxa, 1));
        mxa = fmaxf(mxa, __shfl_xor_sync(~0u, mxa, 2));
        mxb = fmaxf(mxb, __shfl_xor_sync(~0u, mxb, 1));
        mxb = fmaxf(mxb, __shfl_xor_sync(~0u, mxb, 2));

        float mna = fmaxf(m_a, mxa), mnb = fmaxf(m_b, mxb);
        float alpha_a = __expf(m_a - mna), alpha_b = __expf(m_b - mnb);
        float sa = 0.f, sb = 0.f;
        #pragma unroll
        for (int nt = 0; nt < 8; nt++) {
            s[nt][0] = __expf(s[nt][0] - mna);
            s[nt][1] = __expf(s[nt][1] - mna);
            s[nt][2] = __expf(s[nt][2] - mnb);
            s[nt][3] = __expf(s[nt][3] - mnb);
            sa += s[nt][0] + s[nt][1];
            sb += s[nt][2] + s[nt][3];
        }
        sa += __shfl_xor_sync(~0u, sa, 1); sa += __shfl_xor_sync(~0u, sa, 2);
        sb += __shfl_xor_sync(~0u, sb, 1); sb += __shfl_xor_sync(~0u, sb, 2);
        l_a = l_a * alpha_a + sa;
        l_b = l_b * alpha_b + sb;
        m_a = mna; m_b = mnb;

        #pragma unroll
        for (int nt = 0; nt < 16; nt++) {
            o[nt][0] *= alpha_a; o[nt][1] *= alpha_a;
            o[nt][2] *= alpha_b; o[nt][3] *= alpha_b;
        }

        if (jt < jt_end) { CP_WAIT(1); } else { CP_WAIT(0); }
        __syncthreads();

        #pragma unroll
        for (int nt = 0; nt < 8; nt++) {
            int c0 = nt * 8 + tig * 2;
            sP[(r0 + gid) * BNP + kperm(c0)]         = f2tf32(s[nt][0]);
            sP[(r0 + gid) * BNP + kperm(c0 + 1)]     = f2tf32(s[nt][1]);
            sP[(r0 + gid + 8) * BNP + kperm(c0)]     = f2tf32(s[nt][2]);
            sP[(r0 + gid + 8) * BNP + kperm(c0 + 1)] = f2tf32(s[nt][3]);
        }
        __syncwarp();

        #pragma unroll
        for (int kb = 0; kb < ABN; kb += 8) {
            uint32_t a[4];
            uint2 pA = *reinterpret_cast<const uint2*>(&sP[(r0 + gid) * BNP + kb + 2 * tig]);
            uint2 pB = *reinterpret_cast<const uint2*>(&sP[(r0 + gid + 8) * BNP + kb + 2 * tig]);
            a[0] = pA.x; a[2] = pA.y; a[1] = pB.x; a[3] = pB.y;
            #pragma unroll
            for (int nt = 0; nt < 16; nt++) {
                uint32_t b[2];
                b[0] = sV[(kb + tig) * DVP + nt * 8 + gid];
                b[1] = sV[(kb + tig + 4) * DVP + nt * 8 + gid];
                mma_tf32(o[nt], a, b);
            }
        }
    }

    // epilogue: round + K-permute (g_attn is A of out-GEMM)
    const float inv_a = 1.0f / l_a, inv_b = 1.0f / l_b;
    const int rowA = q0 + r0 + gid, rowB = rowA + 8;
    #pragma unroll
    for (int nt = 0; nt < 16; nt++) {
        int cc = h * DVV + nt * 8 + tig * 2;
        int p0 = (cc & ~7) + kperm(cc & 7);
        int p1 = (cc & ~7) + kperm((cc & 7) + 1);
        out[(size_t)rowA * (NH * DVV) + p0] = f2tf32f(o[nt][0] * inv_a);
        out[(size_t)rowA * (NH * DVV) + p1] = f2tf32f(o[nt][1] * inv_a);
        out[(size_t)rowB * (NH * DVV) + p0] = f2tf32f(o[nt][2] * inv_b);
        out[(size_t)rowB * (NH * DVV) + p1] = f2tf32f(o[nt][3] * inv_b);
    }
}

// ---------------- launch --------------------------------------------------------
extern "C" void kernel_launch(void* const* d_in, const int* in_sizes, int n_in,
                              void* d_out, int out_size)
{
    const float* hidden = (const float*)d_in[1];
    const float* w_q    = (const float*)d_in[2];
    const float* w_kv_a = (const float*)d_in[3];
    const float* ln_w   = (const float*)d_in[4];
    const float* w_kv_b = (const float*)d_in[5];
    const float* w_o    = (const float*)d_in[6];
    float* out = (float*)d_out;

    float *q_p, *lat_p, *kva_p, *kpe_p, *kv_p, *attn_p;
    float *hid_r, *wqT, *wkvaT, *wkvbT, *woT;
    cudaGetSymbolAddress((void**)&q_p,    g_q);
    cudaGetSymbolAddress((void**)&lat_p,  g_latent);
    cudaGetSymbolAddress((void**)&kva_p,  g_kva);
    cudaGetSymbolAddress((void**)&kpe_p,  g_kpe);
    cudaGetSymbolAddress((void**)&kv_p,   g_kv);
    cudaGetSymbolAddress((void**)&attn_p, g_attn);
    cudaGetSymbolAddress((void**)&hid_r,  g_hid_r);
    cudaGetSymbolAddress((void**)&wqT,    g_wqT);
    cudaGetSymbolAddress((void**)&wkvaT,  g_wkvaT);
    cudaGetSymbolAddress((void**)&wkvbT,  g_wkvbT);
    cudaGetSymbolAddress((void**)&woT,    g_woT);

    cudaFuncSetAttribute(gemm_tf32_dual,
                         cudaFuncAttributeMaxDynamicSharedMemorySize, GEMM_SMEM);
    cudaFuncSetAttribute(mla_attn_tc,
                         cudaFuncAttributeMaxDynamicSharedMemorySize, ATTN_SMEM);

    dim3 blk(256);

    // prep: hidden rounded+permuted (A); weights transposed+rounded+permuted (B)
    {
        int n = TT * HIDDEN / 8;
        round_permute_copy<<<(n + 255) / 256, blk>>>(hidden, hid_r, n);
        transpose_round_perm<<<dim3(QW / 32, HIDDEN / 32), blk>>>(w_q, wqT, HIDDEN, QW);
        transpose_round_perm<<<dim3(LATW / 32, HIDDEN / 32), blk>>>(w_kv_a, wkvaT, HIDDEN, LATW);
        transpose_round_perm<<<dim3(KVW / 32, KV_LORA / 32), blk>>>(w_kv_b, wkvbT, KV_LORA, KVW);
        transpose_round_perm<<<dim3(HIDDEN / 32, (NH * DVV) / 32), blk>>>(w_o, woT, NH * DVV, HIDDEN);
    }

    const int t1 = QW / 256;                 // 12
    const int t2 = (LATW + 255) / 256;       // 3

    gemm_tf32_dual<<<dim3(t1 + t2, TT / 128), blk, GEMM_SMEM>>>(
        hid_r, wqT, q_p, QW, wkvaT, lat_p, LATW, HIDDEN, 0);
    rmsnorm_ropek_kernel<<<TT, 256>>>(lat_p, ln_w, kva_p, kpe_p);
    gemm_tf32_dual<<<dim3(KVW / 256, TT / 128), blk, GEMM_SMEM>>>(
        kva_p, wkvbT, kv_p, KVW, (const float*)nullptr, (float*)nullptr, 0, KV_LORA, 2);
    mla_attn_tc<<<(TT / ABM) * NH, blk, ATTN_SMEM>>>(q_p, kv_p, kpe_p, attn_p);
    gemm_tf32_dual<<<dim3(HIDDEN / 256, TT / 128), blk, GEMM_SMEM>>>(
        attn_p, woT, out, HIDDEN, (const float*)nullptr, (float*)nullptr, 0, NH * DVV, 0);
}